// round 1
// baseline (speedup 1.0000x reference)
#include <cuda_runtime.h>
#include <stdint.h>

#define N_NODES_MAX 100000
#define D_IN 256
#define D_OUT 256

// Scratch: support = features @ W  (100000 x 256 fp32 = 102.4 MB)
__device__ float g_support[(size_t)N_NODES_MAX * D_OUT];
// Index-dtype flag: 1 = int64 indices, 0 = int32
__device__ int g_idx64;

// ---------------------------------------------------------------------------
// Detect whether adj_row is int64 or int32.
// If int64: values < 2^31 and non-negative, so every odd 32-bit word (high
// half, little-endian) is zero. If int32: those words are random indices in
// [0, 100000) — the chance all 2048 are zero is ~0.
// ---------------------------------------------------------------------------
__global__ void detect_idx_kernel(const unsigned int* __restrict__ words) {
    __shared__ int any_nonzero;
    if (threadIdx.x == 0) any_nonzero = 0;
    __syncthreads();
    int local = 0;
    for (int i = threadIdx.x; i < 2048; i += blockDim.x) {
        if (words[2 * i + 1] != 0u) local = 1;
    }
    if (local) atomicOr(&any_nonzero, 1);
    __syncthreads();
    if (threadIdx.x == 0) g_idx64 = any_nonzero ? 0 : 1;
}

// ---------------------------------------------------------------------------
// Tiled fp32 GEMM: g_support[M, 256] = A[M, 256] @ W[256, 256]
// BM=64, BN=64, BK=16, 256 threads, 4x4 micro-tile per thread.
// ---------------------------------------------------------------------------
#define BM 64
#define BN 64
#define BK 16
#define TM 4
#define TN 4

__global__ __launch_bounds__(256) void gemm_kernel(
    const float* __restrict__ A, const float* __restrict__ W, int M)
{
    __shared__ float As[BK][BM];   // A tile, transposed for conflict-free reads
    __shared__ float Bs[BK][BN];

    const int bm = blockIdx.y * BM;
    const int bn = blockIdx.x * BN;
    const int tid = threadIdx.x;
    const int tx = tid % 16;       // micro-tile col group
    const int ty = tid / 16;       // micro-tile row group

    float acc[TM][TN];
    #pragma unroll
    for (int i = 0; i < TM; i++)
        #pragma unroll
        for (int j = 0; j < TN; j++) acc[i][j] = 0.0f;

    for (int k0 = 0; k0 < D_IN; k0 += BK) {
        // Load A tile: 64 rows x 16 cols = 1024 elems, 4 per thread
        #pragma unroll
        for (int l = 0; l < 4; l++) {
            int idx = tid + l * 256;          // 0..1023
            int row = idx / BK;               // 0..63
            int col = idx % BK;               // 0..15
            int m = bm + row;
            float v = (m < M) ? A[(size_t)m * D_IN + k0 + col] : 0.0f;
            As[col][row] = v;
        }
        // Load W tile: 16 rows x 64 cols = 1024 elems, 4 per thread (coalesced)
        #pragma unroll
        for (int l = 0; l < 4; l++) {
            int idx = tid + l * 256;
            int row = idx / BN;               // 0..15
            int col = idx % BN;               // 0..63
            Bs[row][col] = W[(size_t)(k0 + row) * D_OUT + bn + col];
        }
        __syncthreads();

        #pragma unroll
        for (int k = 0; k < BK; k++) {
            float regM[TM], regN[TN];
            #pragma unroll
            for (int i = 0; i < TM; i++) regM[i] = As[k][ty * TM + i];
            #pragma unroll
            for (int j = 0; j < TN; j++) regN[j] = Bs[k][tx * TN + j];
            #pragma unroll
            for (int i = 0; i < TM; i++)
                #pragma unroll
                for (int j = 0; j < TN; j++)
                    acc[i][j] += regM[i] * regN[j];
        }
        __syncthreads();
    }

    #pragma unroll
    for (int i = 0; i < TM; i++) {
        int m = bm + ty * TM + i;
        if (m < M) {
            float* dst = g_support + (size_t)m * D_OUT + bn + tx * TN;
            #pragma unroll
            for (int j = 0; j < TN; j++) dst[j] = acc[i][j];
        }
    }
}

// ---------------------------------------------------------------------------
// Zero-init the output (harness poisons it with 0xAA).
// ---------------------------------------------------------------------------
__global__ void zero_kernel(float4* __restrict__ out, int n4) {
    int i = blockIdx.x * blockDim.x + threadIdx.x;
    int stride = gridDim.x * blockDim.x;
    for (; i < n4; i += stride) out[i] = make_float4(0.f, 0.f, 0.f, 0.f);
}

// ---------------------------------------------------------------------------
// Edge scatter: one warp per edge.
//   out[row] += val * support[col]   (256 floats, 8 per lane via 2x float4)
// ---------------------------------------------------------------------------
__global__ __launch_bounds__(256) void scatter_kernel(
    const void* __restrict__ adj_row, const void* __restrict__ adj_col,
    const float* __restrict__ adj_val, float* __restrict__ out, int n_edges)
{
    int warp = (blockIdx.x * blockDim.x + threadIdx.x) >> 5;
    int lane = threadIdx.x & 31;
    if (warp >= n_edges) return;

    const int is64 = g_idx64;
    long long r, c;
    if (is64) {
        r = ((const long long*)adj_row)[warp];
        c = ((const long long*)adj_col)[warp];
    } else {
        r = ((const int*)adj_row)[warp];
        c = ((const int*)adj_col)[warp];
    }
    const float v = adj_val[warp];

    const float4* __restrict__ src =
        (const float4*)(g_support + (size_t)c * D_OUT);
    float* __restrict__ dst = out + (size_t)r * D_OUT;

    #pragma unroll
    for (int i = 0; i < 2; i++) {
        int elt = lane + i * 32;          // float4 index 0..63
        float4 s = src[elt];
        int base = elt * 4;
        atomicAdd(dst + base + 0, v * s.x);
        atomicAdd(dst + base + 1, v * s.y);
        atomicAdd(dst + base + 2, v * s.z);
        atomicAdd(dst + base + 3, v * s.w);
    }
}

// ---------------------------------------------------------------------------
// In-place ReLU on the output.
// ---------------------------------------------------------------------------
__global__ void relu_kernel(float4* __restrict__ out, int n4) {
    int i = blockIdx.x * blockDim.x + threadIdx.x;
    int stride = gridDim.x * blockDim.x;
    for (; i < n4; i += stride) {
        float4 v = out[i];
        v.x = fmaxf(v.x, 0.f);
        v.y = fmaxf(v.y, 0.f);
        v.z = fmaxf(v.z, 0.f);
        v.w = fmaxf(v.w, 0.f);
        out[i] = v;
    }
}

// ---------------------------------------------------------------------------
// Launch
// Inputs (metadata order): features f32[N,256], weight f32[256,256],
// adj_row int[E], adj_col int[E], adj_val f32[E]. Output f32[N,256].
// ---------------------------------------------------------------------------
extern "C" void kernel_launch(void* const* d_in, const int* in_sizes, int n_in,
                              void* d_out, int out_size)
{
    const float* features = (const float*)d_in[0];
    const float* weight   = (const float*)d_in[1];
    const void*  adj_row  = d_in[2];
    const void*  adj_col  = d_in[3];
    const float* adj_val  = (const float*)d_in[4];
    float* out = (float*)d_out;

    const int n_nodes = in_sizes[0] / D_IN;
    const int n_edges = in_sizes[4];     // adj_val count — dtype-unambiguous

    // 1. Detect int32 vs int64 indices
    detect_idx_kernel<<<1, 256>>>((const unsigned int*)adj_row);

    // 2. support = features @ W
    dim3 ggrid(D_OUT / BN, (n_nodes + BM - 1) / BM);
    gemm_kernel<<<ggrid, 256>>>(features, weight, n_nodes);

    // 3. Zero output
    int n4 = out_size / 4;
    zero_kernel<<<592, 256>>>((float4*)out, n4);

    // 4. Edge scatter (one warp per edge)
    long long warps = n_edges;
    long long blocks = (warps * 32 + 255) / 256;
    scatter_kernel<<<(unsigned)blocks, 256>>>(adj_row, adj_col, adj_val, out,
                                              n_edges);

    // 5. ReLU
    relu_kernel<<<592, 256>>>((float4*)out, n4);
}

// round 2
// speedup vs baseline: 2.4000x; 2.4000x over previous
#include <cuda_runtime.h>
#include <stdint.h>

#define N_NODES_MAX 100000
#define N_EDGES_MAX 3200000
#define D_IN 256
#define D_OUT 256

// ---------------------------------------------------------------------------
// Static device scratch (no allocations allowed)
// ---------------------------------------------------------------------------
__device__ float g_support[(size_t)N_NODES_MAX * D_OUT];   // features @ W
__device__ uint2 g_edges[N_EDGES_MAX];                     // row-bucketed {col, val}
__device__ int   g_count[N_NODES_MAX + 1];                 // per-row edge counts
__device__ int   g_start[N_NODES_MAX + 1];                 // CSR row starts
__device__ int   g_cursor[N_NODES_MAX];                    // bucket write cursors
__device__ int   g_idx64;                                  // 1 = int64 indices

// ---------------------------------------------------------------------------
// Detect int64 vs int32 indices: int64 node ids < 2^31 have all-zero high words.
// ---------------------------------------------------------------------------
__global__ void detect_idx_kernel(const unsigned int* __restrict__ words) {
    __shared__ int any_nonzero;
    if (threadIdx.x == 0) any_nonzero = 0;
    __syncthreads();
    int local = 0;
    for (int i = threadIdx.x; i < 2048; i += blockDim.x)
        if (words[2 * i + 1] != 0u) local = 1;
    if (local) atomicOr(&any_nonzero, 1);
    __syncthreads();
    if (threadIdx.x == 0) g_idx64 = any_nonzero ? 0 : 1;
}

__device__ __forceinline__ int load_idx(const void* p, int i) {
    return g_idx64 ? (int)((const long long*)p)[i] : ((const int*)p)[i];
}

// ---------------------------------------------------------------------------
// Tiled fp32 GEMM: g_support[M, 256] = A[M, 256] @ W[256, 256]
// ---------------------------------------------------------------------------
#define BM 64
#define BN 64
#define BK 16
#define TM 4
#define TN 4

__global__ __launch_bounds__(256) void gemm_kernel(
    const float* __restrict__ A, const float* __restrict__ W, int M)
{
    __shared__ float As[BK][BM];
    __shared__ float Bs[BK][BN];

    const int bm = blockIdx.y * BM;
    const int bn = blockIdx.x * BN;
    const int tid = threadIdx.x;
    const int tx = tid % 16;
    const int ty = tid / 16;

    float acc[TM][TN];
    #pragma unroll
    for (int i = 0; i < TM; i++)
        #pragma unroll
        for (int j = 0; j < TN; j++) acc[i][j] = 0.0f;

    for (int k0 = 0; k0 < D_IN; k0 += BK) {
        #pragma unroll
        for (int l = 0; l < 4; l++) {
            int idx = tid + l * 256;
            int row = idx / BK, col = idx % BK;
            int m = bm + row;
            As[col][row] = (m < M) ? A[(size_t)m * D_IN + k0 + col] : 0.0f;
        }
        #pragma unroll
        for (int l = 0; l < 4; l++) {
            int idx = tid + l * 256;
            int row = idx / BN, col = idx % BN;
            Bs[row][col] = W[(size_t)(k0 + row) * D_OUT + bn + col];
        }
        __syncthreads();

        #pragma unroll
        for (int k = 0; k < BK; k++) {
            float regM[TM], regN[TN];
            #pragma unroll
            for (int i = 0; i < TM; i++) regM[i] = As[k][ty * TM + i];
            #pragma unroll
            for (int j = 0; j < TN; j++) regN[j] = Bs[k][tx * TN + j];
            #pragma unroll
            for (int i = 0; i < TM; i++)
                #pragma unroll
                for (int j = 0; j < TN; j++)
                    acc[i][j] += regM[i] * regN[j];
        }
        __syncthreads();
    }

    #pragma unroll
    for (int i = 0; i < TM; i++) {
        int m = bm + ty * TM + i;
        if (m < M) {
            float* dst = g_support + (size_t)m * D_OUT + bn + tx * TN;
            #pragma unroll
            for (int j = 0; j < TN; j++) dst[j] = acc[i][j];
        }
    }
}

// ---------------------------------------------------------------------------
// CSR construction: zero counts -> histogram -> scan -> bucket
// ---------------------------------------------------------------------------
__global__ void zero_counts_kernel(int n) {
    int i = blockIdx.x * blockDim.x + threadIdx.x;
    if (i <= n) g_count[i] = 0;
}

__global__ void hist_kernel(const void* __restrict__ adj_row, int n_edges) {
    int e = blockIdx.x * blockDim.x + threadIdx.x;
    if (e >= n_edges) return;
    atomicAdd(&g_count[load_idx(adj_row, e)], 1);
}

// Single-block tiled exclusive scan over n elements; also writes g_cursor and
// the sentinel g_start[n] = total.
__global__ __launch_bounds__(1024) void scan_kernel(int n) {
    __shared__ int sh[1024];
    __shared__ int carry;
    if (threadIdx.x == 0) carry = 0;
    __syncthreads();

    for (int base = 0; base < n; base += 1024) {
        int i = base + threadIdx.x;
        int v = (i < n) ? g_count[i] : 0;
        sh[threadIdx.x] = v;
        __syncthreads();
        #pragma unroll
        for (int off = 1; off < 1024; off <<= 1) {
            int t = (threadIdx.x >= off) ? sh[threadIdx.x - off] : 0;
            __syncthreads();
            sh[threadIdx.x] += t;
            __syncthreads();
        }
        int excl = sh[threadIdx.x] - v + carry;   // carry stable here
        if (i < n) { g_start[i] = excl; g_cursor[i] = excl; }
        __syncthreads();
        if (threadIdx.x == 0) carry += sh[1023];
        __syncthreads();
    }
    if (threadIdx.x == 0) g_start[n] = carry;
}

__global__ void bucket_kernel(const void* __restrict__ adj_row,
                              const void* __restrict__ adj_col,
                              const float* __restrict__ adj_val, int n_edges)
{
    int e = blockIdx.x * blockDim.x + threadIdx.x;
    if (e >= n_edges) return;
    int r = load_idx(adj_row, e);
    int c = load_idx(adj_col, e);
    int pos = atomicAdd(&g_cursor[r], 1);
    g_edges[pos] = make_uint2((unsigned)c, __float_as_uint(adj_val[e]));
}

// ---------------------------------------------------------------------------
// Row accumulate: 64 threads own one row (64 x float4 = 256 floats).
// Block of 256 covers 4 rows. Fused ReLU + store; no atomics, no zero pass.
// ---------------------------------------------------------------------------
__global__ __launch_bounds__(256) void rowacc_kernel(float* __restrict__ out,
                                                     int n_nodes)
{
    const int sub  = threadIdx.x >> 6;      // 0..3
    const int lane = threadIdx.x & 63;      // 0..63
    const int row  = blockIdx.x * 4 + sub;
    if (row >= n_nodes) return;

    const int s = g_start[row];
    const int e = g_start[row + 1];

    float4 acc0 = make_float4(0.f, 0.f, 0.f, 0.f);
    float4 acc1 = make_float4(0.f, 0.f, 0.f, 0.f);

    int i = s;
    // Unroll-by-2 with independent accumulators to expose memory parallelism.
    for (; i + 1 < e; i += 2) {
        uint2 e0 = g_edges[i];
        uint2 e1 = g_edges[i + 1];
        const float4* s0 = (const float4*)(g_support + (size_t)e0.x * D_OUT);
        const float4* s1 = (const float4*)(g_support + (size_t)e1.x * D_OUT);
        float4 t0 = s0[lane];
        float4 t1 = s1[lane];
        float v0 = __uint_as_float(e0.y);
        float v1 = __uint_as_float(e1.y);
        acc0.x += v0 * t0.x; acc0.y += v0 * t0.y;
        acc0.z += v0 * t0.z; acc0.w += v0 * t0.w;
        acc1.x += v1 * t1.x; acc1.y += v1 * t1.y;
        acc1.z += v1 * t1.z; acc1.w += v1 * t1.w;
    }
    if (i < e) {
        uint2 e0 = g_edges[i];
        const float4* s0 = (const float4*)(g_support + (size_t)e0.x * D_OUT);
        float4 t0 = s0[lane];
        float v0 = __uint_as_float(e0.y);
        acc0.x += v0 * t0.x; acc0.y += v0 * t0.y;
        acc0.z += v0 * t0.z; acc0.w += v0 * t0.w;
    }

    float4 r4;
    r4.x = fmaxf(acc0.x + acc1.x, 0.f);
    r4.y = fmaxf(acc0.y + acc1.y, 0.f);
    r4.z = fmaxf(acc0.z + acc1.z, 0.f);
    r4.w = fmaxf(acc0.w + acc1.w, 0.f);
    ((float4*)(out + (size_t)row * D_OUT))[lane] = r4;
}

// ---------------------------------------------------------------------------
// Launch
// ---------------------------------------------------------------------------
extern "C" void kernel_launch(void* const* d_in, const int* in_sizes, int n_in,
                              void* d_out, int out_size)
{
    const float* features = (const float*)d_in[0];
    const float* weight   = (const float*)d_in[1];
    const void*  adj_row  = d_in[2];
    const void*  adj_col  = d_in[3];
    const float* adj_val  = (const float*)d_in[4];
    float* out = (float*)d_out;

    const int n_nodes = in_sizes[0] / D_IN;
    const int n_edges = in_sizes[4];

    // 1. Index dtype detection
    detect_idx_kernel<<<1, 256>>>((const unsigned int*)adj_row);

    // 2. Dense GEMM: support = features @ W
    dim3 ggrid(D_OUT / BN, (n_nodes + BM - 1) / BM);
    gemm_kernel<<<ggrid, 256>>>(features, weight, n_nodes);

    // 3. CSR construction
    zero_counts_kernel<<<(n_nodes + 256) / 256, 256>>>(n_nodes);
    hist_kernel<<<(n_edges + 255) / 256, 256>>>(adj_row, n_edges);
    scan_kernel<<<1, 1024>>>(n_nodes);
    bucket_kernel<<<(n_edges + 255) / 256, 256>>>(adj_row, adj_col, adj_val,
                                                  n_edges);

    // 4. Row gather + fused ReLU
    rowacc_kernel<<<(n_nodes + 3) / 4, 256>>>(out, n_nodes);
}

// round 3
// speedup vs baseline: 4.9176x; 2.0490x over previous
#include <cuda_runtime.h>
#include <stdint.h>

#define N_NODES_MAX 100000
#define N_EDGES_MAX 3200000
#define D_IN 256
#define D_OUT 256

// ---------------------------------------------------------------------------
// Static device scratch
// ---------------------------------------------------------------------------
__device__ float g_support[(size_t)N_NODES_MAX * D_OUT];
__device__ uint2 g_edges[N_EDGES_MAX];
__device__ int   g_count[N_NODES_MAX + 1];
__device__ int   g_start[N_NODES_MAX + 1];
__device__ int   g_cursor[N_NODES_MAX];
__device__ int   g_blocksum[128];
__device__ int   g_blockoff[128];
__device__ int   g_idx64;

// ---------------------------------------------------------------------------
// Index dtype detection
// ---------------------------------------------------------------------------
__global__ void detect_idx_kernel(const unsigned int* __restrict__ words) {
    __shared__ int any_nonzero;
    if (threadIdx.x == 0) any_nonzero = 0;
    __syncthreads();
    int local = 0;
    for (int i = threadIdx.x; i < 2048; i += blockDim.x)
        if (words[2 * i + 1] != 0u) local = 1;
    if (local) atomicOr(&any_nonzero, 1);
    __syncthreads();
    if (threadIdx.x == 0) g_idx64 = any_nonzero ? 0 : 1;
}

__device__ __forceinline__ int load_idx(const void* p, int i) {
    return g_idx64 ? (int)((const long long*)p)[i] : ((const int*)p)[i];
}

__device__ __forceinline__ float tf32r(float x) {
    uint32_t u;
    asm("cvt.rna.tf32.f32 %0, %1;" : "=r"(u) : "f"(x));
    return __uint_as_float(u);
}

// ---------------------------------------------------------------------------
// tf32 tensor-core GEMM: g_support[M,256] = A[M,256] @ W[256,256]
// Block tile 128x128, BK=32, 8 warps (4 along M x 2 along N), warp tile 32x64,
// mma.sync.m16n8k8.tf32. Smem strides picked for conflict-free frag reads.
// ---------------------------------------------------------------------------
#define GM 128
#define GN 128
#define GK 32
#define AS_STRIDE 36   // bank = (4*g + tg) % 32 -> all distinct
#define BS_STRIDE 136  // bank = (8*k + g) % 32 -> all distinct

__global__ __launch_bounds__(256) void gemm_tf32_kernel(
    const float* __restrict__ A, const float* __restrict__ W, int M)
{
    __shared__ __align__(16) float As[GM * AS_STRIDE];
    __shared__ __align__(16) float Bs[GK * BS_STRIDE];

    const int tid  = threadIdx.x;
    const int wid  = tid >> 5;
    const int lane = tid & 31;
    const int g    = lane >> 2;    // groupID
    const int tg   = lane & 3;     // thread-in-group
    const int warp_m = (wid & 3) * 32;
    const int warp_n = (wid >> 2) * 64;
    const int bm = blockIdx.y * GM;
    const int bn = blockIdx.x * GN;

    float c[2][8][4];
    #pragma unroll
    for (int mi = 0; mi < 2; mi++)
        #pragma unroll
        for (int ni = 0; ni < 8; ni++)
            #pragma unroll
            for (int r = 0; r < 4; r++) c[mi][ni][r] = 0.0f;

    for (int k0 = 0; k0 < D_IN; k0 += GK) {
        // A tile: 128 rows x 32 cols = 1024 float4, 4 per thread
        #pragma unroll
        for (int l = 0; l < 4; l++) {
            int idx = tid + l * 256;
            int row = idx >> 3, c4 = idx & 7;
            float4 v = make_float4(0.f, 0.f, 0.f, 0.f);
            int m = bm + row;
            if (m < M) v = *(const float4*)(A + (size_t)m * D_IN + k0 + c4 * 4);
            float4 t = make_float4(tf32r(v.x), tf32r(v.y), tf32r(v.z), tf32r(v.w));
            *(float4*)(As + row * AS_STRIDE + c4 * 4) = t;
        }
        // B tile: 32 rows x 128 cols = 1024 float4, 4 per thread
        #pragma unroll
        for (int l = 0; l < 4; l++) {
            int idx = tid + l * 256;
            int row = idx >> 5, c4 = idx & 31;
            float4 v = *(const float4*)(W + (size_t)(k0 + row) * D_OUT + bn + c4 * 4);
            float4 t = make_float4(tf32r(v.x), tf32r(v.y), tf32r(v.z), tf32r(v.w));
            *(float4*)(Bs + row * BS_STRIDE + c4 * 4) = t;
        }
        __syncthreads();

        #pragma unroll
        for (int ks = 0; ks < 4; ks++) {
            const int kb = ks * 8;
            uint32_t a[2][4], b[8][2];
            #pragma unroll
            for (int mi = 0; mi < 2; mi++) {
                int r = warp_m + mi * 16;
                a[mi][0] = __float_as_uint(As[(r + g)     * AS_STRIDE + kb + tg]);
                a[mi][1] = __float_as_uint(As[(r + g + 8) * AS_STRIDE + kb + tg]);
                a[mi][2] = __float_as_uint(As[(r + g)     * AS_STRIDE + kb + tg + 4]);
                a[mi][3] = __float_as_uint(As[(r + g + 8) * AS_STRIDE + kb + tg + 4]);
            }
            #pragma unroll
            for (int ni = 0; ni < 8; ni++) {
                int col = warp_n + ni * 8 + g;
                b[ni][0] = __float_as_uint(Bs[(kb + tg)     * BS_STRIDE + col]);
                b[ni][1] = __float_as_uint(Bs[(kb + tg + 4) * BS_STRIDE + col]);
            }
            #pragma unroll
            for (int mi = 0; mi < 2; mi++)
                #pragma unroll
                for (int ni = 0; ni < 8; ni++) {
                    asm volatile(
                        "mma.sync.aligned.m16n8k8.row.col.f32.tf32.tf32.f32 "
                        "{%0,%1,%2,%3}, {%4,%5,%6,%7}, {%8,%9}, {%0,%1,%2,%3};\n"
                        : "+f"(c[mi][ni][0]), "+f"(c[mi][ni][1]),
                          "+f"(c[mi][ni][2]), "+f"(c[mi][ni][3])
                        : "r"(a[mi][0]), "r"(a[mi][1]), "r"(a[mi][2]), "r"(a[mi][3]),
                          "r"(b[ni][0]), "r"(b[ni][1]));
                }
        }
        __syncthreads();
    }

    // Epilogue: c0,c1 at (row, col..col+1), c2,c3 at (row+8, col..col+1)
    #pragma unroll
    for (int mi = 0; mi < 2; mi++) {
        int r0 = bm + warp_m + mi * 16 + g;
        #pragma unroll
        for (int ni = 0; ni < 8; ni++) {
            int col = bn + warp_n + ni * 8 + tg * 2;
            if (r0 < M)
                *(float2*)(g_support + (size_t)r0 * D_OUT + col) =
                    make_float2(c[mi][ni][0], c[mi][ni][1]);
            if (r0 + 8 < M)
                *(float2*)(g_support + (size_t)(r0 + 8) * D_OUT + col) =
                    make_float2(c[mi][ni][2], c[mi][ni][3]);
        }
    }
}

// ---------------------------------------------------------------------------
// CSR construction
// ---------------------------------------------------------------------------
__global__ void zero_counts_kernel(int n) {
    int i = blockIdx.x * blockDim.x + threadIdx.x;
    if (i <= n) g_count[i] = 0;
}

__global__ void hist_kernel(const void* __restrict__ adj_row, int n_edges) {
    int e = blockIdx.x * blockDim.x + threadIdx.x;
    if (e >= n_edges) return;
    atomicAdd(&g_count[load_idx(adj_row, e)], 1);
}

// --- Hierarchical exclusive scan: blocksums -> offsets -> scan+write ---
#define SCAN_B 1024

__global__ __launch_bounds__(SCAN_B) void scan_blocksum_kernel(int n) {
    int i = blockIdx.x * SCAN_B + threadIdx.x;
    int lane = threadIdx.x & 31, wid = threadIdx.x >> 5;
    int v = (i < n) ? g_count[i] : 0;
    #pragma unroll
    for (int o = 16; o > 0; o >>= 1) v += __shfl_down_sync(~0u, v, o);
    __shared__ int ws[32];
    if (lane == 0) ws[wid] = v;
    __syncthreads();
    if (wid == 0) {
        int s = ws[lane];
        #pragma unroll
        for (int o = 16; o > 0; o >>= 1) s += __shfl_down_sync(~0u, s, o);
        if (lane == 0) g_blocksum[blockIdx.x] = s;
    }
}

__global__ __launch_bounds__(128) void scan_offsets_kernel(int nb, int n) {
    int tid = threadIdx.x, lane = tid & 31, wid = tid >> 5;
    int v = (tid < nb) ? g_blocksum[tid] : 0;
    int incl = v;
    #pragma unroll
    for (int o = 1; o < 32; o <<= 1) {
        int t = __shfl_up_sync(~0u, incl, o);
        if (lane >= o) incl += t;
    }
    __shared__ int ws[4];
    if (lane == 31) ws[wid] = incl;
    __syncthreads();
    int woff = 0;
    for (int w = 0; w < wid; w++) woff += ws[w];
    incl += woff;
    g_blockoff[tid] = incl - v;            // exclusive block offset
    if (tid == nb - 1) g_start[n] = incl;  // total sentinel
}

__global__ __launch_bounds__(SCAN_B) void scan_write_kernel(int n) {
    int b = blockIdx.x;
    int i = b * SCAN_B + threadIdx.x;
    int lane = threadIdx.x & 31, wid = threadIdx.x >> 5;
    int v = (i < n) ? g_count[i] : 0;
    int incl = v;
    #pragma unroll
    for (int o = 1; o < 32; o <<= 1) {
        int t = __shfl_up_sync(~0u, incl, o);
        if (lane >= o) incl += t;
    }
    __shared__ int ws[32];
    __shared__ int woff[32];
    if (lane == 31) ws[wid] = incl;
    __syncthreads();
    if (wid == 0) {
        int s = ws[lane];
        int si = s;
        #pragma unroll
        for (int o = 1; o < 32; o <<= 1) {
            int t = __shfl_up_sync(~0u, si, o);
            if (lane >= o) si += t;
        }
        woff[lane] = si - s;
    }
    __syncthreads();
    int excl = incl - v + woff[wid] + g_blockoff[b];
    if (i < n) { g_start[i] = excl; g_cursor[i] = excl; }
}

__global__ void bucket_kernel(const void* __restrict__ adj_row,
                              const void* __restrict__ adj_col,
                              const float* __restrict__ adj_val, int n_edges)
{
    int e = blockIdx.x * blockDim.x + threadIdx.x;
    if (e >= n_edges) return;
    int r = load_idx(adj_row, e);
    int c = load_idx(adj_col, e);
    int pos = atomicAdd(&g_cursor[r], 1);
    g_edges[pos] = make_uint2((unsigned)c, __float_as_uint(adj_val[e]));
}

// ---------------------------------------------------------------------------
// Row accumulate: 64 threads per row, fused ReLU, no atomics.
// ---------------------------------------------------------------------------
__global__ __launch_bounds__(256) void rowacc_kernel(float* __restrict__ out,
                                                     int n_nodes)
{
    const int sub  = threadIdx.x >> 6;
    const int lane = threadIdx.x & 63;
    const int row  = blockIdx.x * 4 + sub;
    if (row >= n_nodes) return;

    const int s = g_start[row];
    const int e = g_start[row + 1];

    float4 acc0 = make_float4(0.f, 0.f, 0.f, 0.f);
    float4 acc1 = make_float4(0.f, 0.f, 0.f, 0.f);

    int i = s;
    for (; i + 1 < e; i += 2) {
        uint2 e0 = g_edges[i];
        uint2 e1 = g_edges[i + 1];
        float4 t0 = ((const float4*)(g_support + (size_t)e0.x * D_OUT))[lane];
        float4 t1 = ((const float4*)(g_support + (size_t)e1.x * D_OUT))[lane];
        float v0 = __uint_as_float(e0.y);
        float v1 = __uint_as_float(e1.y);
        acc0.x += v0 * t0.x; acc0.y += v0 * t0.y;
        acc0.z += v0 * t0.z; acc0.w += v0 * t0.w;
        acc1.x += v1 * t1.x; acc1.y += v1 * t1.y;
        acc1.z += v1 * t1.z; acc1.w += v1 * t1.w;
    }
    if (i < e) {
        uint2 e0 = g_edges[i];
        float4 t0 = ((const float4*)(g_support + (size_t)e0.x * D_OUT))[lane];
        float v0 = __uint_as_float(e0.y);
        acc0.x += v0 * t0.x; acc0.y += v0 * t0.y;
        acc0.z += v0 * t0.z; acc0.w += v0 * t0.w;
    }

    float4 r4;
    r4.x = fmaxf(acc0.x + acc1.x, 0.f);
    r4.y = fmaxf(acc0.y + acc1.y, 0.f);
    r4.z = fmaxf(acc0.z + acc1.z, 0.f);
    r4.w = fmaxf(acc0.w + acc1.w, 0.f);
    ((float4*)(out + (size_t)row * D_OUT))[lane] = r4;
}

// ---------------------------------------------------------------------------
// Launch
// ---------------------------------------------------------------------------
extern "C" void kernel_launch(void* const* d_in, const int* in_sizes, int n_in,
                              void* d_out, int out_size)
{
    const float* features = (const float*)d_in[0];
    const float* weight   = (const float*)d_in[1];
    const void*  adj_row  = d_in[2];
    const void*  adj_col  = d_in[3];
    const float* adj_val  = (const float*)d_in[4];
    float* out = (float*)d_out;

    const int n_nodes = in_sizes[0] / D_IN;
    const int n_edges = in_sizes[4];

    detect_idx_kernel<<<1, 256>>>((const unsigned int*)adj_row);

    dim3 ggrid(D_OUT / GN, (n_nodes + GM - 1) / GM);
    gemm_tf32_kernel<<<ggrid, 256>>>(features, weight, n_nodes);

    zero_counts_kernel<<<(n_nodes + 256) / 256, 256>>>(n_nodes);
    hist_kernel<<<(n_edges + 255) / 256, 256>>>(adj_row, n_edges);

    int nb = (n_nodes + SCAN_B - 1) / SCAN_B;
    scan_blocksum_kernel<<<nb, SCAN_B>>>(n_nodes);
    scan_offsets_kernel<<<1, 128>>>(nb, n_nodes);
    scan_write_kernel<<<nb, SCAN_B>>>(n_nodes);

    bucket_kernel<<<(n_edges + 255) / 256, 256>>>(adj_row, adj_col, adj_val,
                                                  n_edges);

    rowacc_kernel<<<(n_nodes + 3) / 4, 256>>>(out, n_nodes);
}

// round 4
// speedup vs baseline: 6.0918x; 1.2388x over previous
#include <cuda_runtime.h>
#include <stdint.h>

#define N_NODES_MAX 100000
#define N_EDGES_MAX 3200000
#define D_IN 256
#define D_OUT 256

#if defined(CUDA_API_PER_THREAD_DEFAULT_STREAM) || defined(__CUDA_API_PER_THREAD_DEFAULT_STREAM__)
#define DEF_STREAM cudaStreamPerThread
#else
#define DEF_STREAM cudaStreamLegacy
#endif

// ---------------------------------------------------------------------------
// Static device scratch
// ---------------------------------------------------------------------------
__device__ float g_support[(size_t)N_NODES_MAX * D_OUT];
__device__ uint2 g_edges[N_EDGES_MAX];
__device__ int   g_count[N_NODES_MAX + 1];
__device__ int   g_start[N_NODES_MAX + 1];
__device__ int   g_cursor[N_NODES_MAX];
__device__ int   g_blocksum[128];
__device__ int   g_blockoff[128];
__device__ int   g_idx64;

// ---------------------------------------------------------------------------
// Index dtype detection (int64 node ids < 2^31 -> all-zero high words)
// ---------------------------------------------------------------------------
__global__ void detect_idx_kernel(const unsigned int* __restrict__ words) {
    __shared__ int any_nonzero;
    if (threadIdx.x == 0) any_nonzero = 0;
    __syncthreads();
    int local = 0;
    for (int i = threadIdx.x; i < 2048; i += blockDim.x)
        if (words[2 * i + 1] != 0u) local = 1;
    if (local) atomicOr(&any_nonzero, 1);
    __syncthreads();
    if (threadIdx.x == 0) g_idx64 = any_nonzero ? 0 : 1;
}

__device__ __forceinline__ int load_idx(const void* p, int i) {
    return g_idx64 ? (int)((const long long*)p)[i] : ((const int*)p)[i];
}

__device__ __forceinline__ float tf32r(float x) {
    uint32_t u;
    asm("cvt.rna.tf32.f32 %0, %1;" : "=r"(u) : "f"(x));
    return __uint_as_float(u);
}

// ---------------------------------------------------------------------------
// tf32 tensor-core GEMM: g_support[M,256] = A[M,256] @ W[256,256]
// (unchanged from R3 — verified at rel_err 2.9e-4)
// ---------------------------------------------------------------------------
#define GM 128
#define GN 128
#define GK 32
#define AS_STRIDE 36
#define BS_STRIDE 136

__global__ __launch_bounds__(256) void gemm_tf32_kernel(
    const float* __restrict__ A, const float* __restrict__ W, int M)
{
    __shared__ __align__(16) float As[GM * AS_STRIDE];
    __shared__ __align__(16) float Bs[GK * BS_STRIDE];

    const int tid  = threadIdx.x;
    const int wid  = tid >> 5;
    const int lane = tid & 31;
    const int g    = lane >> 2;
    const int tg   = lane & 3;
    const int warp_m = (wid & 3) * 32;
    const int warp_n = (wid >> 2) * 64;
    const int bm = blockIdx.y * GM;
    const int bn = blockIdx.x * GN;

    float c[2][8][4];
    #pragma unroll
    for (int mi = 0; mi < 2; mi++)
        #pragma unroll
        for (int ni = 0; ni < 8; ni++)
            #pragma unroll
            for (int r = 0; r < 4; r++) c[mi][ni][r] = 0.0f;

    for (int k0 = 0; k0 < D_IN; k0 += GK) {
        #pragma unroll
        for (int l = 0; l < 4; l++) {
            int idx = tid + l * 256;
            int row = idx >> 3, c4 = idx & 7;
            float4 v = make_float4(0.f, 0.f, 0.f, 0.f);
            int m = bm + row;
            if (m < M) v = *(const float4*)(A + (size_t)m * D_IN + k0 + c4 * 4);
            float4 t = make_float4(tf32r(v.x), tf32r(v.y), tf32r(v.z), tf32r(v.w));
            *(float4*)(As + row * AS_STRIDE + c4 * 4) = t;
        }
        #pragma unroll
        for (int l = 0; l < 4; l++) {
            int idx = tid + l * 256;
            int row = idx >> 5, c4 = idx & 31;
            float4 v = *(const float4*)(W + (size_t)(k0 + row) * D_OUT + bn + c4 * 4);
            float4 t = make_float4(tf32r(v.x), tf32r(v.y), tf32r(v.z), tf32r(v.w));
            *(float4*)(Bs + row * BS_STRIDE + c4 * 4) = t;
        }
        __syncthreads();

        #pragma unroll
        for (int ks = 0; ks < 4; ks++) {
            const int kb = ks * 8;
            uint32_t a[2][4], b[8][2];
            #pragma unroll
            for (int mi = 0; mi < 2; mi++) {
                int r = warp_m + mi * 16;
                a[mi][0] = __float_as_uint(As[(r + g)     * AS_STRIDE + kb + tg]);
                a[mi][1] = __float_as_uint(As[(r + g + 8) * AS_STRIDE + kb + tg]);
                a[mi][2] = __float_as_uint(As[(r + g)     * AS_STRIDE + kb + tg + 4]);
                a[mi][3] = __float_as_uint(As[(r + g + 8) * AS_STRIDE + kb + tg + 4]);
            }
            #pragma unroll
            for (int ni = 0; ni < 8; ni++) {
                int col = warp_n + ni * 8 + g;
                b[ni][0] = __float_as_uint(Bs[(kb + tg)     * BS_STRIDE + col]);
                b[ni][1] = __float_as_uint(Bs[(kb + tg + 4) * BS_STRIDE + col]);
            }
            #pragma unroll
            for (int mi = 0; mi < 2; mi++)
                #pragma unroll
                for (int ni = 0; ni < 8; ni++) {
                    asm volatile(
                        "mma.sync.aligned.m16n8k8.row.col.f32.tf32.tf32.f32 "
                        "{%0,%1,%2,%3}, {%4,%5,%6,%7}, {%8,%9}, {%0,%1,%2,%3};\n"
                        : "+f"(c[mi][ni][0]), "+f"(c[mi][ni][1]),
                          "+f"(c[mi][ni][2]), "+f"(c[mi][ni][3])
                        : "r"(a[mi][0]), "r"(a[mi][1]), "r"(a[mi][2]), "r"(a[mi][3]),
                          "r"(b[ni][0]), "r"(b[ni][1]));
                }
        }
        __syncthreads();
    }

    #pragma unroll
    for (int mi = 0; mi < 2; mi++) {
        int r0 = bm + warp_m + mi * 16 + g;
        #pragma unroll
        for (int ni = 0; ni < 8; ni++) {
            int col = bn + warp_n + ni * 8 + tg * 2;
            if (r0 < M)
                *(float2*)(g_support + (size_t)r0 * D_OUT + col) =
                    make_float2(c[mi][ni][0], c[mi][ni][1]);
            if (r0 + 8 < M)
                *(float2*)(g_support + (size_t)(r0 + 8) * D_OUT + col) =
                    make_float2(c[mi][ni][2], c[mi][ni][3]);
        }
    }
}

// ---------------------------------------------------------------------------
// CSR construction
// ---------------------------------------------------------------------------
__global__ void zero_counts_kernel(int n) {
    int i = blockIdx.x * blockDim.x + threadIdx.x;
    if (i <= n) g_count[i] = 0;
}

__global__ void hist_kernel(const void* __restrict__ adj_row, int n_edges) {
    int e = blockIdx.x * blockDim.x + threadIdx.x;
    if (e >= n_edges) return;
    atomicAdd(&g_count[load_idx(adj_row, e)], 1);
}

#define SCAN_B 1024

__global__ __launch_bounds__(SCAN_B) void scan_blocksum_kernel(int n) {
    int i = blockIdx.x * SCAN_B + threadIdx.x;
    int lane = threadIdx.x & 31, wid = threadIdx.x >> 5;
    int v = (i < n) ? g_count[i] : 0;
    #pragma unroll
    for (int o = 16; o > 0; o >>= 1) v += __shfl_down_sync(~0u, v, o);
    __shared__ int ws[32];
    if (lane == 0) ws[wid] = v;
    __syncthreads();
    if (wid == 0) {
        int s = ws[lane];
        #pragma unroll
        for (int o = 16; o > 0; o >>= 1) s += __shfl_down_sync(~0u, s, o);
        if (lane == 0) g_blocksum[blockIdx.x] = s;
    }
}

__global__ __launch_bounds__(128) void scan_offsets_kernel(int nb, int n) {
    int tid = threadIdx.x, lane = tid & 31, wid = tid >> 5;
    int v = (tid < nb) ? g_blocksum[tid] : 0;
    int incl = v;
    #pragma unroll
    for (int o = 1; o < 32; o <<= 1) {
        int t = __shfl_up_sync(~0u, incl, o);
        if (lane >= o) incl += t;
    }
    __shared__ int ws[4];
    if (lane == 31) ws[wid] = incl;
    __syncthreads();
    int woff = 0;
    for (int w = 0; w < wid; w++) woff += ws[w];
    incl += woff;
    g_blockoff[tid] = incl - v;
    if (tid == nb - 1) g_start[n] = incl;
}

__global__ __launch_bounds__(SCAN_B) void scan_write_kernel(int n) {
    int b = blockIdx.x;
    int i = b * SCAN_B + threadIdx.x;
    int lane = threadIdx.x & 31, wid = threadIdx.x >> 5;
    int v = (i < n) ? g_count[i] : 0;
    int incl = v;
    #pragma unroll
    for (int o = 1; o < 32; o <<= 1) {
        int t = __shfl_up_sync(~0u, incl, o);
        if (lane >= o) incl += t;
    }
    __shared__ int ws[32];
    __shared__ int woff[32];
    if (lane == 31) ws[wid] = incl;
    __syncthreads();
    if (wid == 0) {
        int s = ws[lane];
        int si = s;
        #pragma unroll
        for (int o = 1; o < 32; o <<= 1) {
            int t = __shfl_up_sync(~0u, si, o);
            if (lane >= o) si += t;
        }
        woff[lane] = si - s;
    }
    __syncthreads();
    int excl = incl - v + woff[wid] + g_blockoff[b];
    if (i < n) { g_start[i] = excl; g_cursor[i] = excl; }
}

__global__ void bucket_kernel(const void* __restrict__ adj_row,
                              const void* __restrict__ adj_col,
                              const float* __restrict__ adj_val, int n_edges)
{
    int e = blockIdx.x * blockDim.x + threadIdx.x;
    if (e >= n_edges) return;
    int r = load_idx(adj_row, e);
    int c = load_idx(adj_col, e);
    int pos = atomicAdd(&g_cursor[r], 1);
    g_edges[pos] = make_uint2((unsigned)c, __float_as_uint(adj_val[e]));
}

// ---------------------------------------------------------------------------
// Row accumulate, column-chunked: pass covers 128 of 256 output columns so the
// gathered support slice (51.2 MB) stays L2-resident. 32 lanes per row,
// 8 rows per block. Fused ReLU; streaming stores keep L2 clean.
// ---------------------------------------------------------------------------
__global__ __launch_bounds__(256) void rowacc_kernel(float* __restrict__ out,
                                                     int n_nodes, int coff)
{
    const int sub  = threadIdx.x >> 5;      // 0..7
    const int lane = threadIdx.x & 31;      // 0..31 -> 32 x float4 = 128 cols
    const int row  = blockIdx.x * 8 + sub;
    if (row >= n_nodes) return;

    const int s = g_start[row];
    const int e = g_start[row + 1];

    float4 acc0 = make_float4(0.f, 0.f, 0.f, 0.f);
    float4 acc1 = make_float4(0.f, 0.f, 0.f, 0.f);

    int i = s;
    for (; i + 1 < e; i += 2) {
        uint2 e0 = g_edges[i];
        uint2 e1 = g_edges[i + 1];
        float4 t0 = ((const float4*)(g_support + (size_t)e0.x * D_OUT + coff))[lane];
        float4 t1 = ((const float4*)(g_support + (size_t)e1.x * D_OUT + coff))[lane];
        float v0 = __uint_as_float(e0.y);
        float v1 = __uint_as_float(e1.y);
        acc0.x += v0 * t0.x; acc0.y += v0 * t0.y;
        acc0.z += v0 * t0.z; acc0.w += v0 * t0.w;
        acc1.x += v1 * t1.x; acc1.y += v1 * t1.y;
        acc1.z += v1 * t1.z; acc1.w += v1 * t1.w;
    }
    if (i < e) {
        uint2 e0 = g_edges[i];
        float4 t0 = ((const float4*)(g_support + (size_t)e0.x * D_OUT + coff))[lane];
        float v0 = __uint_as_float(e0.y);
        acc0.x += v0 * t0.x; acc0.y += v0 * t0.y;
        acc0.z += v0 * t0.z; acc0.w += v0 * t0.w;
    }

    float4 r4;
    r4.x = fmaxf(acc0.x + acc1.x, 0.f);
    r4.y = fmaxf(acc0.y + acc1.y, 0.f);
    r4.z = fmaxf(acc0.z + acc1.z, 0.f);
    r4.w = fmaxf(acc0.w + acc1.w, 0.f);
    __stcs((float4*)(out + (size_t)row * D_OUT + coff) + lane, r4);
}

// ---------------------------------------------------------------------------
// Launch: fork CSR chain onto a side stream so it overlaps the GEMM.
// Stream/events created once (host resources only, no device memory).
// ---------------------------------------------------------------------------
extern "C" void kernel_launch(void* const* d_in, const int* in_sizes, int n_in,
                              void* d_out, int out_size)
{
    static cudaStream_t s2 = nullptr;
    static cudaEvent_t ev_fork = nullptr, ev_join = nullptr;
    static bool tried = false;
    if (!tried) {
        tried = true;
        if (cudaStreamCreateWithFlags(&s2, cudaStreamNonBlocking) != cudaSuccess)
            s2 = nullptr;
        if (s2) {
            if (cudaEventCreateWithFlags(&ev_fork, cudaEventDisableTiming) != cudaSuccess ||
                cudaEventCreateWithFlags(&ev_join, cudaEventDisableTiming) != cudaSuccess)
                s2 = nullptr;
        }
    }
    const bool use2 = (s2 != nullptr);
    cudaStream_t cs = use2 ? s2 : DEF_STREAM;

    const float* features = (const float*)d_in[0];
    const float* weight   = (const float*)d_in[1];
    const void*  adj_row  = d_in[2];
    const void*  adj_col  = d_in[3];
    const float* adj_val  = (const float*)d_in[4];
    float* out = (float*)d_out;

    const int n_nodes = in_sizes[0] / D_IN;
    const int n_edges = in_sizes[4];

    // Detection feeds both branches — run before the fork.
    detect_idx_kernel<<<1, 256>>>((const unsigned int*)adj_row);

    if (use2) {
        cudaEventRecord(ev_fork, DEF_STREAM);
        cudaStreamWaitEvent(s2, ev_fork, 0);
    }

    // --- Branch A (side stream): CSR construction ---
    zero_counts_kernel<<<(n_nodes + 256) / 256, 256, 0, cs>>>(n_nodes);
    hist_kernel<<<(n_edges + 255) / 256, 256, 0, cs>>>(adj_row, n_edges);
    int nb = (n_nodes + SCAN_B - 1) / SCAN_B;
    scan_blocksum_kernel<<<nb, SCAN_B, 0, cs>>>(n_nodes);
    scan_offsets_kernel<<<1, 128, 0, cs>>>(nb, n_nodes);
    scan_write_kernel<<<nb, SCAN_B, 0, cs>>>(n_nodes);
    bucket_kernel<<<(n_edges + 255) / 256, 256, 0, cs>>>(adj_row, adj_col,
                                                         adj_val, n_edges);

    // --- Branch B (default stream): dense GEMM ---
    dim3 ggrid(D_OUT / GN, (n_nodes + GM - 1) / GM);
    gemm_tf32_kernel<<<ggrid, 256>>>(features, weight, n_nodes);

    if (use2) {
        cudaEventRecord(ev_join, s2);
        cudaStreamWaitEvent(DEF_STREAM, ev_join, 0);
    }

    // --- Join: column-chunked row gather + fused ReLU ---
    int rblocks = (n_nodes + 7) / 8;
    rowacc_kernel<<<rblocks, 256>>>(out, n_nodes, 0);
    rowacc_kernel<<<rblocks, 256>>>(out, n_nodes, 128);
}

// round 5
// speedup vs baseline: 7.8441x; 1.2876x over previous
#include <cuda_runtime.h>
#include <cuda_fp16.h>
#include <stdint.h>

#define N_NODES_MAX 100000
#define N_EDGES_MAX 3200000
#define D_IN 256
#define D_OUT 256

#if defined(CUDA_API_PER_THREAD_DEFAULT_STREAM) || defined(__CUDA_API_PER_THREAD_DEFAULT_STREAM__)
#define DEF_STREAM cudaStreamPerThread
#else
#define DEF_STREAM cudaStreamLegacy
#endif

// ---------------------------------------------------------------------------
// Static device scratch
// ---------------------------------------------------------------------------
__device__ __half g_support_h[(size_t)N_NODES_MAX * D_OUT];  // fp16 support (51.2 MB)
__device__ uint2  g_edges[N_EDGES_MAX];                      // row-bucketed {col, val}
__device__ int    g_count[N_NODES_MAX + 1];
__device__ int    g_start[N_NODES_MAX + 1];
__device__ int    g_cursor[N_NODES_MAX];
__device__ int    g_blocksum[128];
__device__ int    g_blockoff[128];
__device__ int    g_idx64;

// ---------------------------------------------------------------------------
// Index dtype detection (int64 node ids < 2^31 -> all-zero high words)
// ---------------------------------------------------------------------------
__global__ void detect_idx_kernel(const unsigned int* __restrict__ words) {
    __shared__ int any_nonzero;
    if (threadIdx.x == 0) any_nonzero = 0;
    __syncthreads();
    int local = 0;
    for (int i = threadIdx.x; i < 2048; i += blockDim.x)
        if (words[2 * i + 1] != 0u) local = 1;
    if (local) atomicOr(&any_nonzero, 1);
    __syncthreads();
    if (threadIdx.x == 0) g_idx64 = any_nonzero ? 0 : 1;
}

__device__ __forceinline__ int load_idx(const void* p, int i) {
    return g_idx64 ? (int)((const long long*)p)[i] : ((const int*)p)[i];
}

__device__ __forceinline__ float tf32r(float x) {
    uint32_t u;
    asm("cvt.rna.tf32.f32 %0, %1;" : "=r"(u) : "f"(x));
    return __uint_as_float(u);
}

// ---------------------------------------------------------------------------
// tf32 tensor-core GEMM: g_support_h[M,256] = fp16(A[M,256] @ W[256,256])
// ---------------------------------------------------------------------------
#define GM 128
#define GN 128
#define GK 32
#define AS_STRIDE 36
#define BS_STRIDE 136

__global__ __launch_bounds__(256) void gemm_tf32_kernel(
    const float* __restrict__ A, const float* __restrict__ W, int M)
{
    __shared__ __align__(16) float As[GM * AS_STRIDE];
    __shared__ __align__(16) float Bs[GK * BS_STRIDE];

    const int tid  = threadIdx.x;
    const int wid  = tid >> 5;
    const int lane = tid & 31;
    const int g    = lane >> 2;
    const int tg   = lane & 3;
    const int warp_m = (wid & 3) * 32;
    const int warp_n = (wid >> 2) * 64;
    const int bm = blockIdx.y * GM;
    const int bn = blockIdx.x * GN;

    float c[2][8][4];
    #pragma unroll
    for (int mi = 0; mi < 2; mi++)
        #pragma unroll
        for (int ni = 0; ni < 8; ni++)
            #pragma unroll
            for (int r = 0; r < 4; r++) c[mi][ni][r] = 0.0f;

    for (int k0 = 0; k0 < D_IN; k0 += GK) {
        #pragma unroll
        for (int l = 0; l < 4; l++) {
            int idx = tid + l * 256;
            int row = idx >> 3, c4 = idx & 7;
            float4 v = make_float4(0.f, 0.f, 0.f, 0.f);
            int m = bm + row;
            if (m < M) v = *(const float4*)(A + (size_t)m * D_IN + k0 + c4 * 4);
            float4 t = make_float4(tf32r(v.x), tf32r(v.y), tf32r(v.z), tf32r(v.w));
            *(float4*)(As + row * AS_STRIDE + c4 * 4) = t;
        }
        #pragma unroll
        for (int l = 0; l < 4; l++) {
            int idx = tid + l * 256;
            int row = idx >> 5, c4 = idx & 31;
            float4 v = *(const float4*)(W + (size_t)(k0 + row) * D_OUT + bn + c4 * 4);
            float4 t = make_float4(tf32r(v.x), tf32r(v.y), tf32r(v.z), tf32r(v.w));
            *(float4*)(Bs + row * BS_STRIDE + c4 * 4) = t;
        }
        __syncthreads();

        #pragma unroll
        for (int ks = 0; ks < 4; ks++) {
            const int kb = ks * 8;
            uint32_t a[2][4], b[8][2];
            #pragma unroll
            for (int mi = 0; mi < 2; mi++) {
                int r = warp_m + mi * 16;
                a[mi][0] = __float_as_uint(As[(r + g)     * AS_STRIDE + kb + tg]);
                a[mi][1] = __float_as_uint(As[(r + g + 8) * AS_STRIDE + kb + tg]);
                a[mi][2] = __float_as_uint(As[(r + g)     * AS_STRIDE + kb + tg + 4]);
                a[mi][3] = __float_as_uint(As[(r + g + 8) * AS_STRIDE + kb + tg + 4]);
            }
            #pragma unroll
            for (int ni = 0; ni < 8; ni++) {
                int col = warp_n + ni * 8 + g;
                b[ni][0] = __float_as_uint(Bs[(kb + tg)     * BS_STRIDE + col]);
                b[ni][1] = __float_as_uint(Bs[(kb + tg + 4) * BS_STRIDE + col]);
            }
            #pragma unroll
            for (int mi = 0; mi < 2; mi++)
                #pragma unroll
                for (int ni = 0; ni < 8; ni++) {
                    asm volatile(
                        "mma.sync.aligned.m16n8k8.row.col.f32.tf32.tf32.f32 "
                        "{%0,%1,%2,%3}, {%4,%5,%6,%7}, {%8,%9}, {%0,%1,%2,%3};\n"
                        : "+f"(c[mi][ni][0]), "+f"(c[mi][ni][1]),
                          "+f"(c[mi][ni][2]), "+f"(c[mi][ni][3])
                        : "r"(a[mi][0]), "r"(a[mi][1]), "r"(a[mi][2]), "r"(a[mi][3]),
                          "r"(b[ni][0]), "r"(b[ni][1]));
                }
        }
        __syncthreads();
    }

    // Epilogue: convert to fp16, store __half2 pairs (col even -> 4B aligned)
    #pragma unroll
    for (int mi = 0; mi < 2; mi++) {
        int r0 = bm + warp_m + mi * 16 + g;
        #pragma unroll
        for (int ni = 0; ni < 8; ni++) {
            int col = bn + warp_n + ni * 8 + tg * 2;
            if (r0 < M)
                *(__half2*)(g_support_h + (size_t)r0 * D_OUT + col) =
                    __floats2half2_rn(c[mi][ni][0], c[mi][ni][1]);
            if (r0 + 8 < M)
                *(__half2*)(g_support_h + (size_t)(r0 + 8) * D_OUT + col) =
                    __floats2half2_rn(c[mi][ni][2], c[mi][ni][3]);
        }
    }
}

// ---------------------------------------------------------------------------
// CSR construction
// ---------------------------------------------------------------------------
__global__ void zero_counts_kernel(int n) {
    int i = blockIdx.x * blockDim.x + threadIdx.x;
    if (i <= n) g_count[i] = 0;
}

__global__ void hist_kernel(const void* __restrict__ adj_row, int n_edges) {
    int e = blockIdx.x * blockDim.x + threadIdx.x;
    if (e >= n_edges) return;
    atomicAdd(&g_count[load_idx(adj_row, e)], 1);
}

#define SCAN_B 1024

__global__ __launch_bounds__(SCAN_B) void scan_blocksum_kernel(int n) {
    int i = blockIdx.x * SCAN_B + threadIdx.x;
    int lane = threadIdx.x & 31, wid = threadIdx.x >> 5;
    int v = (i < n) ? g_count[i] : 0;
    #pragma unroll
    for (int o = 16; o > 0; o >>= 1) v += __shfl_down_sync(~0u, v, o);
    __shared__ int ws[32];
    if (lane == 0) ws[wid] = v;
    __syncthreads();
    if (wid == 0) {
        int s = ws[lane];
        #pragma unroll
        for (int o = 16; o > 0; o >>= 1) s += __shfl_down_sync(~0u, s, o);
        if (lane == 0) g_blocksum[blockIdx.x] = s;
    }
}

__global__ __launch_bounds__(128) void scan_offsets_kernel(int nb, int n) {
    int tid = threadIdx.x, lane = tid & 31, wid = tid >> 5;
    int v = (tid < nb) ? g_blocksum[tid] : 0;
    int incl = v;
    #pragma unroll
    for (int o = 1; o < 32; o <<= 1) {
        int t = __shfl_up_sync(~0u, incl, o);
        if (lane >= o) incl += t;
    }
    __shared__ int ws[4];
    if (lane == 31) ws[wid] = incl;
    __syncthreads();
    int woff = 0;
    for (int w = 0; w < wid; w++) woff += ws[w];
    incl += woff;
    g_blockoff[tid] = incl - v;
    if (tid == nb - 1) g_start[n] = incl;
}

__global__ __launch_bounds__(SCAN_B) void scan_write_kernel(int n) {
    int b = blockIdx.x;
    int i = b * SCAN_B + threadIdx.x;
    int lane = threadIdx.x & 31, wid = threadIdx.x >> 5;
    int v = (i < n) ? g_count[i] : 0;
    int incl = v;
    #pragma unroll
    for (int o = 1; o < 32; o <<= 1) {
        int t = __shfl_up_sync(~0u, incl, o);
        if (lane >= o) incl += t;
    }
    __shared__ int ws[32];
    __shared__ int woff[32];
    if (lane == 31) ws[wid] = incl;
    __syncthreads();
    if (wid == 0) {
        int s = ws[lane];
        int si = s;
        #pragma unroll
        for (int o = 1; o < 32; o <<= 1) {
            int t = __shfl_up_sync(~0u, si, o);
            if (lane >= o) si += t;
        }
        woff[lane] = si - s;
    }
    __syncthreads();
    int excl = incl - v + woff[wid] + g_blockoff[b];
    if (i < n) { g_start[i] = excl; g_cursor[i] = excl; }
}

__global__ void bucket_kernel(const void* __restrict__ adj_row,
                              const void* __restrict__ adj_col,
                              const float* __restrict__ adj_val, int n_edges)
{
    int e = blockIdx.x * blockDim.x + threadIdx.x;
    if (e >= n_edges) return;
    int r = load_idx(adj_row, e);
    int c = load_idx(adj_col, e);
    int pos = atomicAdd(&g_cursor[r], 1);
    g_edges[pos] = make_uint2((unsigned)c, __float_as_uint(adj_val[e]));
}

// ---------------------------------------------------------------------------
// Row accumulate, single pass over fp16 support (51.2 MB -> L2-resident).
// 32 lanes per row; each lane owns 8 consecutive output cols (uint4 = 8 halves).
// fp32 accumulation, fused ReLU, streaming stores.
// ---------------------------------------------------------------------------
__global__ __launch_bounds__(256) void rowacc_kernel(float* __restrict__ out,
                                                     int n_nodes)
{
    const int sub  = threadIdx.x >> 5;      // 0..7
    const int lane = threadIdx.x & 31;
    const int row  = blockIdx.x * 8 + sub;
    if (row >= n_nodes) return;

    const int s = g_start[row];
    const int e = g_start[row + 1];

    float acc0[8], acc1[8];
    #pragma unroll
    for (int k = 0; k < 8; k++) { acc0[k] = 0.f; acc1[k] = 0.f; }

    int i = s;
    for (; i + 1 < e; i += 2) {
        uint2 e0 = g_edges[i];
        uint2 e1 = g_edges[i + 1];
        uint4 h0 = ((const uint4*)(g_support_h + (size_t)e0.x * D_OUT))[lane];
        uint4 h1 = ((const uint4*)(g_support_h + (size_t)e1.x * D_OUT))[lane];
        float v0 = __uint_as_float(e0.y);
        float v1 = __uint_as_float(e1.y);

        float2 f;
        f = __half22float2(*(__half2*)&h0.x); acc0[0] += v0*f.x; acc0[1] += v0*f.y;
        f = __half22float2(*(__half2*)&h0.y); acc0[2] += v0*f.x; acc0[3] += v0*f.y;
        f = __half22float2(*(__half2*)&h0.z); acc0[4] += v0*f.x; acc0[5] += v0*f.y;
        f = __half22float2(*(__half2*)&h0.w); acc0[6] += v0*f.x; acc0[7] += v0*f.y;
        f = __half22float2(*(__half2*)&h1.x); acc1[0] += v1*f.x; acc1[1] += v1*f.y;
        f = __half22float2(*(__half2*)&h1.y); acc1[2] += v1*f.x; acc1[3] += v1*f.y;
        f = __half22float2(*(__half2*)&h1.z); acc1[4] += v1*f.x; acc1[5] += v1*f.y;
        f = __half22float2(*(__half2*)&h1.w); acc1[6] += v1*f.x; acc1[7] += v1*f.y;
    }
    if (i < e) {
        uint2 e0 = g_edges[i];
        uint4 h0 = ((const uint4*)(g_support_h + (size_t)e0.x * D_OUT))[lane];
        float v0 = __uint_as_float(e0.y);
        float2 f;
        f = __half22float2(*(__half2*)&h0.x); acc0[0] += v0*f.x; acc0[1] += v0*f.y;
        f = __half22float2(*(__half2*)&h0.y); acc0[2] += v0*f.x; acc0[3] += v0*f.y;
        f = __half22float2(*(__half2*)&h0.z); acc0[4] += v0*f.x; acc0[5] += v0*f.y;
        f = __half22float2(*(__half2*)&h0.w); acc0[6] += v0*f.x; acc0[7] += v0*f.y;
    }

    float4 ra, rb;
    ra.x = fmaxf(acc0[0] + acc1[0], 0.f);
    ra.y = fmaxf(acc0[1] + acc1[1], 0.f);
    ra.z = fmaxf(acc0[2] + acc1[2], 0.f);
    ra.w = fmaxf(acc0[3] + acc1[3], 0.f);
    rb.x = fmaxf(acc0[4] + acc1[4], 0.f);
    rb.y = fmaxf(acc0[5] + acc1[5], 0.f);
    rb.z = fmaxf(acc0[6] + acc1[6], 0.f);
    rb.w = fmaxf(acc0[7] + acc1[7], 0.f);

    float* dst = out + (size_t)row * D_OUT + lane * 8;
    __stcs((float4*)dst,     ra);
    __stcs((float4*)dst + 1, rb);
}

// ---------------------------------------------------------------------------
// Launch: CSR chain forked onto side stream, overlapping the GEMM.
// ---------------------------------------------------------------------------
extern "C" void kernel_launch(void* const* d_in, const int* in_sizes, int n_in,
                              void* d_out, int out_size)
{
    static cudaStream_t s2 = nullptr;
    static cudaEvent_t ev_fork = nullptr, ev_join = nullptr;
    static bool tried = false;
    if (!tried) {
        tried = true;
        if (cudaStreamCreateWithFlags(&s2, cudaStreamNonBlocking) != cudaSuccess)
            s2 = nullptr;
        if (s2) {
            if (cudaEventCreateWithFlags(&ev_fork, cudaEventDisableTiming) != cudaSuccess ||
                cudaEventCreateWithFlags(&ev_join, cudaEventDisableTiming) != cudaSuccess)
                s2 = nullptr;
        }
    }
    const bool use2 = (s2 != nullptr);
    cudaStream_t cs = use2 ? s2 : DEF_STREAM;

    const float* features = (const float*)d_in[0];
    const float* weight   = (const float*)d_in[1];
    const void*  adj_row  = d_in[2];
    const void*  adj_col  = d_in[3];
    const float* adj_val  = (const float*)d_in[4];
    float* out = (float*)d_out;

    const int n_nodes = in_sizes[0] / D_IN;
    const int n_edges = in_sizes[4];

    detect_idx_kernel<<<1, 256>>>((const unsigned int*)adj_row);

    if (use2) {
        cudaEventRecord(ev_fork, DEF_STREAM);
        cudaStreamWaitEvent(s2, ev_fork, 0);
    }

    // --- Branch A (side stream): CSR construction ---
    zero_counts_kernel<<<(n_nodes + 256) / 256, 256, 0, cs>>>(n_nodes);
    hist_kernel<<<(n_edges + 255) / 256, 256, 0, cs>>>(adj_row, n_edges);
    int nb = (n_nodes + SCAN_B - 1) / SCAN_B;
    scan_blocksum_kernel<<<nb, SCAN_B, 0, cs>>>(n_nodes);
    scan_offsets_kernel<<<1, 128, 0, cs>>>(nb, n_nodes);
    scan_write_kernel<<<nb, SCAN_B, 0, cs>>>(n_nodes);
    bucket_kernel<<<(n_edges + 255) / 256, 256, 0, cs>>>(adj_row, adj_col,
                                                         adj_val, n_edges);

    // --- Branch B (default stream): dense GEMM -> fp16 support ---
    dim3 ggrid(D_OUT / GN, (n_nodes + GM - 1) / GM);
    gemm_tf32_kernel<<<ggrid, 256>>>(features, weight, n_nodes);

    if (use2) {
        cudaEventRecord(ev_join, s2);
        cudaStreamWaitEvent(DEF_STREAM, ev_join, 0);
    }

    // --- Join: single-pass row gather + fused ReLU ---
    rowacc_kernel<<<(n_nodes + 7) / 8, 256>>>(out, n_nodes);
}

// round 6
// speedup vs baseline: 8.0059x; 1.0206x over previous
#include <cuda_runtime.h>
#include <cuda_fp16.h>
#include <stdint.h>

#define N_NODES_MAX 100000
#define N_EDGES_MAX 3200000
#define D_IN 256
#define D_OUT 256

#if defined(CUDA_API_PER_THREAD_DEFAULT_STREAM) || defined(__CUDA_API_PER_THREAD_DEFAULT_STREAM__)
#define DEF_STREAM cudaStreamPerThread
#else
#define DEF_STREAM cudaStreamLegacy
#endif

// ---------------------------------------------------------------------------
// Static device scratch
// ---------------------------------------------------------------------------
__device__ __half g_support_h[(size_t)N_NODES_MAX * D_OUT];  // fp16 support (51.2 MB)
__device__ uint2  g_edges[N_EDGES_MAX];                      // row-bucketed {col, val}
__device__ int    g_count[N_NODES_MAX + 1];
__device__ int    g_start[N_NODES_MAX + 1];
__device__ int    g_cursor[N_NODES_MAX];
__device__ int    g_blocksum[128];
__device__ int    g_blockoff[128];
__device__ int    g_idx64;

// ---------------------------------------------------------------------------
// Index dtype detection
// ---------------------------------------------------------------------------
__global__ void detect_idx_kernel(const unsigned int* __restrict__ words) {
    __shared__ int any_nonzero;
    if (threadIdx.x == 0) any_nonzero = 0;
    __syncthreads();
    int local = 0;
    for (int i = threadIdx.x; i < 2048; i += blockDim.x)
        if (words[2 * i + 1] != 0u) local = 1;
    if (local) atomicOr(&any_nonzero, 1);
    __syncthreads();
    if (threadIdx.x == 0) g_idx64 = any_nonzero ? 0 : 1;
}

__device__ __forceinline__ int load_idx(const void* p, int i) {
    return g_idx64 ? (int)((const long long*)p)[i] : ((const int*)p)[i];
}

__device__ __forceinline__ float tf32r(float x) {
    uint32_t u;
    asm("cvt.rna.tf32.f32 %0, %1;" : "=r"(u) : "f"(x));
    return __uint_as_float(u);
}

// ---------------------------------------------------------------------------
// tf32 tensor-core GEMM: g_support_h[M,256] = fp16(A[M,256] @ W[256,256])
// ---------------------------------------------------------------------------
#define GM 128
#define GN 128
#define GK 32
#define AS_STRIDE 36
#define BS_STRIDE 136

__global__ __launch_bounds__(256) void gemm_tf32_kernel(
    const float* __restrict__ A, const float* __restrict__ W, int M)
{
    __shared__ __align__(16) float As[GM * AS_STRIDE];
    __shared__ __align__(16) float Bs[GK * BS_STRIDE];

    const int tid  = threadIdx.x;
    const int wid  = tid >> 5;
    const int lane = tid & 31;
    const int g    = lane >> 2;
    const int tg   = lane & 3;
    const int warp_m = (wid & 3) * 32;
    const int warp_n = (wid >> 2) * 64;
    const int bm = blockIdx.y * GM;
    const int bn = blockIdx.x * GN;

    float c[2][8][4];
    #pragma unroll
    for (int mi = 0; mi < 2; mi++)
        #pragma unroll
        for (int ni = 0; ni < 8; ni++)
            #pragma unroll
            for (int r = 0; r < 4; r++) c[mi][ni][r] = 0.0f;

    for (int k0 = 0; k0 < D_IN; k0 += GK) {
        #pragma unroll
        for (int l = 0; l < 4; l++) {
            int idx = tid + l * 256;
            int row = idx >> 3, c4 = idx & 7;
            float4 v = make_float4(0.f, 0.f, 0.f, 0.f);
            int m = bm + row;
            if (m < M) v = *(const float4*)(A + (size_t)m * D_IN + k0 + c4 * 4);
            float4 t = make_float4(tf32r(v.x), tf32r(v.y), tf32r(v.z), tf32r(v.w));
            *(float4*)(As + row * AS_STRIDE + c4 * 4) = t;
        }
        #pragma unroll
        for (int l = 0; l < 4; l++) {
            int idx = tid + l * 256;
            int row = idx >> 5, c4 = idx & 31;
            float4 v = *(const float4*)(W + (size_t)(k0 + row) * D_OUT + bn + c4 * 4);
            float4 t = make_float4(tf32r(v.x), tf32r(v.y), tf32r(v.z), tf32r(v.w));
            *(float4*)(Bs + row * BS_STRIDE + c4 * 4) = t;
        }
        __syncthreads();

        #pragma unroll
        for (int ks = 0; ks < 4; ks++) {
            const int kb = ks * 8;
            uint32_t a[2][4], b[8][2];
            #pragma unroll
            for (int mi = 0; mi < 2; mi++) {
                int r = warp_m + mi * 16;
                a[mi][0] = __float_as_uint(As[(r + g)     * AS_STRIDE + kb + tg]);
                a[mi][1] = __float_as_uint(As[(r + g + 8) * AS_STRIDE + kb + tg]);
                a[mi][2] = __float_as_uint(As[(r + g)     * AS_STRIDE + kb + tg + 4]);
                a[mi][3] = __float_as_uint(As[(r + g + 8) * AS_STRIDE + kb + tg + 4]);
            }
            #pragma unroll
            for (int ni = 0; ni < 8; ni++) {
                int col = warp_n + ni * 8 + g;
                b[ni][0] = __float_as_uint(Bs[(kb + tg)     * BS_STRIDE + col]);
                b[ni][1] = __float_as_uint(Bs[(kb + tg + 4) * BS_STRIDE + col]);
            }
            #pragma unroll
            for (int mi = 0; mi < 2; mi++)
                #pragma unroll
                for (int ni = 0; ni < 8; ni++) {
                    asm volatile(
                        "mma.sync.aligned.m16n8k8.row.col.f32.tf32.tf32.f32 "
                        "{%0,%1,%2,%3}, {%4,%5,%6,%7}, {%8,%9}, {%0,%1,%2,%3};\n"
                        : "+f"(c[mi][ni][0]), "+f"(c[mi][ni][1]),
                          "+f"(c[mi][ni][2]), "+f"(c[mi][ni][3])
                        : "r"(a[mi][0]), "r"(a[mi][1]), "r"(a[mi][2]), "r"(a[mi][3]),
                          "r"(b[ni][0]), "r"(b[ni][1]));
                }
        }
        __syncthreads();
    }

    #pragma unroll
    for (int mi = 0; mi < 2; mi++) {
        int r0 = bm + warp_m + mi * 16 + g;
        #pragma unroll
        for (int ni = 0; ni < 8; ni++) {
            int col = bn + warp_n + ni * 8 + tg * 2;
            if (r0 < M)
                *(__half2*)(g_support_h + (size_t)r0 * D_OUT + col) =
                    __floats2half2_rn(c[mi][ni][0], c[mi][ni][1]);
            if (r0 + 8 < M)
                *(__half2*)(g_support_h + (size_t)(r0 + 8) * D_OUT + col) =
                    __floats2half2_rn(c[mi][ni][2], c[mi][ni][3]);
        }
    }
}

// ---------------------------------------------------------------------------
// CSR construction
// ---------------------------------------------------------------------------
__global__ void zero_counts_kernel(int n) {
    int i = blockIdx.x * blockDim.x + threadIdx.x;
    if (i <= n) g_count[i] = 0;
}

// 4 edges per thread to raise load MLP; atomics unchanged (spread addresses).
__global__ void hist_kernel(const void* __restrict__ adj_row, int n_edges) {
    int base = (blockIdx.x * blockDim.x + threadIdx.x) * 4;
    #pragma unroll
    for (int k = 0; k < 4; k++) {
        int e = base + k;
        if (e < n_edges) atomicAdd(&g_count[load_idx(adj_row, e)], 1);
    }
}

#define SCAN_B 1024

__global__ __launch_bounds__(SCAN_B) void scan_blocksum_kernel(int n) {
    int i = blockIdx.x * SCAN_B + threadIdx.x;
    int lane = threadIdx.x & 31, wid = threadIdx.x >> 5;
    int v = (i < n) ? g_count[i] : 0;
    #pragma unroll
    for (int o = 16; o > 0; o >>= 1) v += __shfl_down_sync(~0u, v, o);
    __shared__ int ws[32];
    if (lane == 0) ws[wid] = v;
    __syncthreads();
    if (wid == 0) {
        int s = ws[lane];
        #pragma unroll
        for (int o = 16; o > 0; o >>= 1) s += __shfl_down_sync(~0u, s, o);
        if (lane == 0) g_blocksum[blockIdx.x] = s;
    }
}

__global__ __launch_bounds__(128) void scan_offsets_kernel(int nb, int n) {
    int tid = threadIdx.x, lane = tid & 31, wid = tid >> 5;
    int v = (tid < nb) ? g_blocksum[tid] : 0;
    int incl = v;
    #pragma unroll
    for (int o = 1; o < 32; o <<= 1) {
        int t = __shfl_up_sync(~0u, incl, o);
        if (lane >= o) incl += t;
    }
    __shared__ int ws[4];
    if (lane == 31) ws[wid] = incl;
    __syncthreads();
    int woff = 0;
    for (int w = 0; w < wid; w++) woff += ws[w];
    incl += woff;
    g_blockoff[tid] = incl - v;
    if (tid == nb - 1) g_start[n] = incl;
}

__global__ __launch_bounds__(SCAN_B) void scan_write_kernel(int n) {
    int b = blockIdx.x;
    int i = b * SCAN_B + threadIdx.x;
    int lane = threadIdx.x & 31, wid = threadIdx.x >> 5;
    int v = (i < n) ? g_count[i] : 0;
    int incl = v;
    #pragma unroll
    for (int o = 1; o < 32; o <<= 1) {
        int t = __shfl_up_sync(~0u, incl, o);
        if (lane >= o) incl += t;
    }
    __shared__ int ws[32];
    __shared__ int woff[32];
    if (lane == 31) ws[wid] = incl;
    __syncthreads();
    if (wid == 0) {
        int s = ws[lane];
        int si = s;
        #pragma unroll
        for (int o = 1; o < 32; o <<= 1) {
            int t = __shfl_up_sync(~0u, si, o);
            if (lane >= o) si += t;
        }
        woff[lane] = si - s;
    }
    __syncthreads();
    int excl = incl - v + woff[wid] + g_blockoff[b];
    if (i < n) { g_start[i] = excl; g_cursor[i] = excl; }
}

__global__ void bucket_kernel(const void* __restrict__ adj_row,
                              const void* __restrict__ adj_col,
                              const float* __restrict__ adj_val, int n_edges)
{
    int e = blockIdx.x * blockDim.x + threadIdx.x;
    if (e >= n_edges) return;
    int r = load_idx(adj_row, e);
    int c = load_idx(adj_col, e);
    int pos = atomicAdd(&g_cursor[r], 1);
    g_edges[pos] = make_uint2((unsigned)c, __float_as_uint(adj_val[e]));
}

// ---------------------------------------------------------------------------
// Row accumulate: unroll-4 with batched edge prefetch -> 4 independent 512B
// gathers in flight per warp (MLP=4, LTS-saturating). fp32 accumulation,
// fused ReLU, streaming stores.
// ---------------------------------------------------------------------------
__device__ __forceinline__ void acc_half8(float* acc, uint4 h, float v) {
    float2 f;
    f = __half22float2(*(__half2*)&h.x); acc[0] += v * f.x; acc[1] += v * f.y;
    f = __half22float2(*(__half2*)&h.y); acc[2] += v * f.x; acc[3] += v * f.y;
    f = __half22float2(*(__half2*)&h.z); acc[4] += v * f.x; acc[5] += v * f.y;
    f = __half22float2(*(__half2*)&h.w); acc[6] += v * f.x; acc[7] += v * f.y;
}

__global__ __launch_bounds__(256) void rowacc_kernel(float* __restrict__ out,
                                                     int n_nodes)
{
    const int sub  = threadIdx.x >> 5;      // 0..7
    const int lane = threadIdx.x & 31;
    const int row  = blockIdx.x * 8 + sub;
    if (row >= n_nodes) return;

    const int s = g_start[row];
    const int e = g_start[row + 1];

    float acc0[8], acc1[8];
    #pragma unroll
    for (int k = 0; k < 8; k++) { acc0[k] = 0.f; acc1[k] = 0.f; }

    int i = s;
    for (; i + 3 < e; i += 4) {
        // Batch-load 4 edge records (broadcast across the warp — cheap)
        uint2 e0 = __ldg(&g_edges[i]);
        uint2 e1 = __ldg(&g_edges[i + 1]);
        uint2 e2 = __ldg(&g_edges[i + 2]);
        uint2 e3 = __ldg(&g_edges[i + 3]);
        // 4 independent gathers in flight
        uint4 h0 = __ldg((const uint4*)(g_support_h + (size_t)e0.x * D_OUT) + lane);
        uint4 h1 = __ldg((const uint4*)(g_support_h + (size_t)e1.x * D_OUT) + lane);
        uint4 h2 = __ldg((const uint4*)(g_support_h + (size_t)e2.x * D_OUT) + lane);
        uint4 h3 = __ldg((const uint4*)(g_support_h + (size_t)e3.x * D_OUT) + lane);

        acc_half8(acc0, h0, __uint_as_float(e0.y));
        acc_half8(acc1, h1, __uint_as_float(e1.y));
        acc_half8(acc0, h2, __uint_as_float(e2.y));
        acc_half8(acc1, h3, __uint_as_float(e3.y));
    }
    for (; i < e; i++) {
        uint2 e0 = __ldg(&g_edges[i]);
        uint4 h0 = __ldg((const uint4*)(g_support_h + (size_t)e0.x * D_OUT) + lane);
        acc_half8(acc0, h0, __uint_as_float(e0.y));
    }

    float4 ra, rb;
    ra.x = fmaxf(acc0[0] + acc1[0], 0.f);
    ra.y = fmaxf(acc0[1] + acc1[1], 0.f);
    ra.z = fmaxf(acc0[2] + acc1[2], 0.f);
    ra.w = fmaxf(acc0[3] + acc1[3], 0.f);
    rb.x = fmaxf(acc0[4] + acc1[4], 0.f);
    rb.y = fmaxf(acc0[5] + acc1[5], 0.f);
    rb.z = fmaxf(acc0[6] + acc1[6], 0.f);
    rb.w = fmaxf(acc0[7] + acc1[7], 0.f);

    float* dst = out + (size_t)row * D_OUT + lane * 8;
    __stcs((float4*)dst,     ra);
    __stcs((float4*)dst + 1, rb);
}

// ---------------------------------------------------------------------------
// Launch: CSR chain forked onto side stream, overlapping the GEMM.
// ---------------------------------------------------------------------------
extern "C" void kernel_launch(void* const* d_in, const int* in_sizes, int n_in,
                              void* d_out, int out_size)
{
    static cudaStream_t s2 = nullptr;
    static cudaEvent_t ev_fork = nullptr, ev_join = nullptr;
    static bool tried = false;
    if (!tried) {
        tried = true;
        if (cudaStreamCreateWithFlags(&s2, cudaStreamNonBlocking) != cudaSuccess)
            s2 = nullptr;
        if (s2) {
            if (cudaEventCreateWithFlags(&ev_fork, cudaEventDisableTiming) != cudaSuccess ||
                cudaEventCreateWithFlags(&ev_join, cudaEventDisableTiming) != cudaSuccess)
                s2 = nullptr;
        }
    }
    const bool use2 = (s2 != nullptr);
    cudaStream_t cs = use2 ? s2 : DEF_STREAM;

    const float* features = (const float*)d_in[0];
    const float* weight   = (const float*)d_in[1];
    const void*  adj_row  = d_in[2];
    const void*  adj_col  = d_in[3];
    const float* adj_val  = (const float*)d_in[4];
    float* out = (float*)d_out;

    const int n_nodes = in_sizes[0] / D_IN;
    const int n_edges = in_sizes[4];

    detect_idx_kernel<<<1, 256>>>((const unsigned int*)adj_row);

    if (use2) {
        cudaEventRecord(ev_fork, DEF_STREAM);
        cudaStreamWaitEvent(s2, ev_fork, 0);
    }

    // --- Branch A (side stream): CSR construction ---
    zero_counts_kernel<<<(n_nodes + 256) / 256, 256, 0, cs>>>(n_nodes);
    hist_kernel<<<(n_edges + 1023) / 1024, 256, 0, cs>>>(adj_row, n_edges);
    int nb = (n_nodes + SCAN_B - 1) / SCAN_B;
    scan_blocksum_kernel<<<nb, SCAN_B, 0, cs>>>(n_nodes);
    scan_offsets_kernel<<<1, 128, 0, cs>>>(nb, n_nodes);
    scan_write_kernel<<<nb, SCAN_B, 0, cs>>>(n_nodes);
    bucket_kernel<<<(n_edges + 255) / 256, 256, 0, cs>>>(adj_row, adj_col,
                                                         adj_val, n_edges);

    // --- Branch B (default stream): dense GEMM -> fp16 support ---
    dim3 ggrid(D_OUT / GN, (n_nodes + GM - 1) / GM);
    gemm_tf32_kernel<<<ggrid, 256>>>(features, weight, n_nodes);

    if (use2) {
        cudaEventRecord(ev_join, s2);
        cudaStreamWaitEvent(DEF_STREAM, ev_join, 0);
    }

    // --- Join: single-pass row gather + fused ReLU ---
    rowacc_kernel<<<(n_nodes + 7) / 8, 256>>>(out, n_nodes);
}

// round 7
// speedup vs baseline: 8.0893x; 1.0104x over previous
#include <cuda_runtime.h>
#include <cuda_fp16.h>
#include <stdint.h>

#define N_NODES_MAX 100000
#define N_EDGES_MAX 3200000
#define D_IN 256
#define D_OUT 256

#if defined(CUDA_API_PER_THREAD_DEFAULT_STREAM) || defined(__CUDA_API_PER_THREAD_DEFAULT_STREAM__)
#define DEF_STREAM cudaStreamPerThread
#else
#define DEF_STREAM cudaStreamLegacy
#endif

// ---------------------------------------------------------------------------
// Static device scratch
// ---------------------------------------------------------------------------
__device__ __half g_support_h[(size_t)N_NODES_MAX * D_OUT];  // fp16 support
__device__ uint2  g_edges[N_EDGES_MAX];
__device__ int    g_count[N_NODES_MAX + 1];
__device__ int    g_start[N_NODES_MAX + 1];
__device__ int    g_cursor[N_NODES_MAX];
__device__ int    g_blocksum[128];
__device__ int    g_blockoff[128];
__device__ int    g_idx64;

// ---------------------------------------------------------------------------
// Index dtype detection
// ---------------------------------------------------------------------------
__global__ void detect_idx_kernel(const unsigned int* __restrict__ words) {
    __shared__ int any_nonzero;
    if (threadIdx.x == 0) any_nonzero = 0;
    __syncthreads();
    int local = 0;
    for (int i = threadIdx.x; i < 2048; i += blockDim.x)
        if (words[2 * i + 1] != 0u) local = 1;
    if (local) atomicOr(&any_nonzero, 1);
    __syncthreads();
    if (threadIdx.x == 0) g_idx64 = any_nonzero ? 0 : 1;
}

__device__ __forceinline__ int load_idx(const void* p, int i) {
    return g_idx64 ? (int)((const long long*)p)[i] : ((const int*)p)[i];
}

__device__ __forceinline__ float tf32r(float x) {
    uint32_t u;
    asm("cvt.rna.tf32.f32 %0, %1;" : "=r"(u) : "f"(x));
    return __uint_as_float(u);
}

// ---------------------------------------------------------------------------
// tf32 tensor-core GEMM over a 128-column slice of W:
//   g_support_h[M, bn0:bn0+128] = fp16(A[M,256] @ W[:, bn0:bn0+128])
// ---------------------------------------------------------------------------
#define GM 128
#define GN 128
#define GK 32
#define AS_STRIDE 36
#define BS_STRIDE 136

__global__ __launch_bounds__(256) void gemm_tf32_kernel(
    const float* __restrict__ A, const float* __restrict__ W, int M, int bn0)
{
    __shared__ __align__(16) float As[GM * AS_STRIDE];
    __shared__ __align__(16) float Bs[GK * BS_STRIDE];

    const int tid  = threadIdx.x;
    const int wid  = tid >> 5;
    const int lane = tid & 31;
    const int g    = lane >> 2;
    const int tg   = lane & 3;
    const int warp_m = (wid & 3) * 32;
    const int warp_n = (wid >> 2) * 64;
    const int bm = blockIdx.y * GM;
    const int bn = bn0;

    float c[2][8][4];
    #pragma unroll
    for (int mi = 0; mi < 2; mi++)
        #pragma unroll
        for (int ni = 0; ni < 8; ni++)
            #pragma unroll
            for (int r = 0; r < 4; r++) c[mi][ni][r] = 0.0f;

    for (int k0 = 0; k0 < D_IN; k0 += GK) {
        #pragma unroll
        for (int l = 0; l < 4; l++) {
            int idx = tid + l * 256;
            int row = idx >> 3, c4 = idx & 7;
            float4 v = make_float4(0.f, 0.f, 0.f, 0.f);
            int m = bm + row;
            if (m < M) v = *(const float4*)(A + (size_t)m * D_IN + k0 + c4 * 4);
            float4 t = make_float4(tf32r(v.x), tf32r(v.y), tf32r(v.z), tf32r(v.w));
            *(float4*)(As + row * AS_STRIDE + c4 * 4) = t;
        }
        #pragma unroll
        for (int l = 0; l < 4; l++) {
            int idx = tid + l * 256;
            int row = idx >> 5, c4 = idx & 31;
            float4 v = *(const float4*)(W + (size_t)(k0 + row) * D_OUT + bn + c4 * 4);
            float4 t = make_float4(tf32r(v.x), tf32r(v.y), tf32r(v.z), tf32r(v.w));
            *(float4*)(Bs + row * BS_STRIDE + c4 * 4) = t;
        }
        __syncthreads();

        #pragma unroll
        for (int ks = 0; ks < 4; ks++) {
            const int kb = ks * 8;
            uint32_t a[2][4], b[8][2];
            #pragma unroll
            for (int mi = 0; mi < 2; mi++) {
                int r = warp_m + mi * 16;
                a[mi][0] = __float_as_uint(As[(r + g)     * AS_STRIDE + kb + tg]);
                a[mi][1] = __float_as_uint(As[(r + g + 8) * AS_STRIDE + kb + tg]);
                a[mi][2] = __float_as_uint(As[(r + g)     * AS_STRIDE + kb + tg + 4]);
                a[mi][3] = __float_as_uint(As[(r + g + 8) * AS_STRIDE + kb + tg + 4]);
            }
            #pragma unroll
            for (int ni = 0; ni < 8; ni++) {
                int col = warp_n + ni * 8 + g;
                b[ni][0] = __float_as_uint(Bs[(kb + tg)     * BS_STRIDE + col]);
                b[ni][1] = __float_as_uint(Bs[(kb + tg + 4) * BS_STRIDE + col]);
            }
            #pragma unroll
            for (int mi = 0; mi < 2; mi++)
                #pragma unroll
                for (int ni = 0; ni < 8; ni++) {
                    asm volatile(
                        "mma.sync.aligned.m16n8k8.row.col.f32.tf32.tf32.f32 "
                        "{%0,%1,%2,%3}, {%4,%5,%6,%7}, {%8,%9}, {%0,%1,%2,%3};\n"
                        : "+f"(c[mi][ni][0]), "+f"(c[mi][ni][1]),
                          "+f"(c[mi][ni][2]), "+f"(c[mi][ni][3])
                        : "r"(a[mi][0]), "r"(a[mi][1]), "r"(a[mi][2]), "r"(a[mi][3]),
                          "r"(b[ni][0]), "r"(b[ni][1]));
                }
        }
        __syncthreads();
    }

    #pragma unroll
    for (int mi = 0; mi < 2; mi++) {
        int r0 = bm + warp_m + mi * 16 + g;
        #pragma unroll
        for (int ni = 0; ni < 8; ni++) {
            int col = bn + warp_n + ni * 8 + tg * 2;
            if (r0 < M)
                *(__half2*)(g_support_h + (size_t)r0 * D_OUT + col) =
                    __floats2half2_rn(c[mi][ni][0], c[mi][ni][1]);
            if (r0 + 8 < M)
                *(__half2*)(g_support_h + (size_t)(r0 + 8) * D_OUT + col) =
                    __floats2half2_rn(c[mi][ni][2], c[mi][ni][3]);
        }
    }
}

// ---------------------------------------------------------------------------
// CSR construction
// ---------------------------------------------------------------------------
__global__ void zero_counts_kernel(int n) {
    int i = blockIdx.x * blockDim.x + threadIdx.x;
    if (i <= n) g_count[i] = 0;
}

__global__ void hist_kernel(const void* __restrict__ adj_row, int n_edges) {
    int base = (blockIdx.x * blockDim.x + threadIdx.x) * 4;
    #pragma unroll
    for (int k = 0; k < 4; k++) {
        int e = base + k;
        if (e < n_edges) atomicAdd(&g_count[load_idx(adj_row, e)], 1);
    }
}

#define SCAN_B 1024

__global__ __launch_bounds__(SCAN_B) void scan_blocksum_kernel(int n) {
    int i = blockIdx.x * SCAN_B + threadIdx.x;
    int lane = threadIdx.x & 31, wid = threadIdx.x >> 5;
    int v = (i < n) ? g_count[i] : 0;
    #pragma unroll
    for (int o = 16; o > 0; o >>= 1) v += __shfl_down_sync(~0u, v, o);
    __shared__ int ws[32];
    if (lane == 0) ws[wid] = v;
    __syncthreads();
    if (wid == 0) {
        int s = ws[lane];
        #pragma unroll
        for (int o = 16; o > 0; o >>= 1) s += __shfl_down_sync(~0u, s, o);
        if (lane == 0) g_blocksum[blockIdx.x] = s;
    }
}

__global__ __launch_bounds__(128) void scan_offsets_kernel(int nb, int n) {
    int tid = threadIdx.x, lane = tid & 31, wid = tid >> 5;
    int v = (tid < nb) ? g_blocksum[tid] : 0;
    int incl = v;
    #pragma unroll
    for (int o = 1; o < 32; o <<= 1) {
        int t = __shfl_up_sync(~0u, incl, o);
        if (lane >= o) incl += t;
    }
    __shared__ int ws[4];
    if (lane == 31) ws[wid] = incl;
    __syncthreads();
    int woff = 0;
    for (int w = 0; w < wid; w++) woff += ws[w];
    incl += woff;
    g_blockoff[tid] = incl - v;
    if (tid == nb - 1) g_start[n] = incl;
}

__global__ __launch_bounds__(SCAN_B) void scan_write_kernel(int n) {
    int b = blockIdx.x;
    int i = b * SCAN_B + threadIdx.x;
    int lane = threadIdx.x & 31, wid = threadIdx.x >> 5;
    int v = (i < n) ? g_count[i] : 0;
    int incl = v;
    #pragma unroll
    for (int o = 1; o < 32; o <<= 1) {
        int t = __shfl_up_sync(~0u, incl, o);
        if (lane >= o) incl += t;
    }
    __shared__ int ws[32];
    __shared__ int woff[32];
    if (lane == 31) ws[wid] = incl;
    __syncthreads();
    if (wid == 0) {
        int s = ws[lane];
        int si = s;
        #pragma unroll
        for (int o = 1; o < 32; o <<= 1) {
            int t = __shfl_up_sync(~0u, si, o);
            if (lane >= o) si += t;
        }
        woff[lane] = si - s;
    }
    __syncthreads();
    int excl = incl - v + woff[wid] + g_blockoff[b];
    if (i < n) { g_start[i] = excl; g_cursor[i] = excl; }
}

__global__ void bucket_kernel(const void* __restrict__ adj_row,
                              const void* __restrict__ adj_col,
                              const float* __restrict__ adj_val, int n_edges)
{
    int e = blockIdx.x * blockDim.x + threadIdx.x;
    if (e >= n_edges) return;
    int r = load_idx(adj_row, e);
    int c = load_idx(adj_col, e);
    int pos = atomicAdd(&g_cursor[r], 1);
    g_edges[pos] = make_uint2((unsigned)c, __float_as_uint(adj_val[e]));
}

// ---------------------------------------------------------------------------
// Row accumulate over a 128-column slice (coff = 0 or 128). 32 lanes per row,
// each lane owns 4 consecutive cols (uint2 = 4 halves). Gather = 256B/edge
// (2x128B lines). fp32 accumulation, fused ReLU, streaming stores.
// ---------------------------------------------------------------------------
__device__ __forceinline__ void acc_half4(float* acc, uint2 h, float v) {
    float2 f;
    f = __half22float2(*(__half2*)&h.x); acc[0] += v * f.x; acc[1] += v * f.y;
    f = __half22float2(*(__half2*)&h.y); acc[2] += v * f.x; acc[3] += v * f.y;
}

__global__ __launch_bounds__(256) void rowacc_kernel(float* __restrict__ out,
                                                     int n_nodes, int coff)
{
    const int sub  = threadIdx.x >> 5;      // 0..7
    const int lane = threadIdx.x & 31;
    const int row  = blockIdx.x * 8 + sub;
    if (row >= n_nodes) return;

    const int s = g_start[row];
    const int e = g_start[row + 1];

    float acc0[4], acc1[4];
    #pragma unroll
    for (int k = 0; k < 4; k++) { acc0[k] = 0.f; acc1[k] = 0.f; }

    int i = s;
    for (; i + 3 < e; i += 4) {
        uint2 e0 = __ldg(&g_edges[i]);
        uint2 e1 = __ldg(&g_edges[i + 1]);
        uint2 e2 = __ldg(&g_edges[i + 2]);
        uint2 e3 = __ldg(&g_edges[i + 3]);
        uint2 h0 = __ldg((const uint2*)(g_support_h + (size_t)e0.x * D_OUT + coff) + lane);
        uint2 h1 = __ldg((const uint2*)(g_support_h + (size_t)e1.x * D_OUT + coff) + lane);
        uint2 h2 = __ldg((const uint2*)(g_support_h + (size_t)e2.x * D_OUT + coff) + lane);
        uint2 h3 = __ldg((const uint2*)(g_support_h + (size_t)e3.x * D_OUT + coff) + lane);

        acc_half4(acc0, h0, __uint_as_float(e0.y));
        acc_half4(acc1, h1, __uint_as_float(e1.y));
        acc_half4(acc0, h2, __uint_as_float(e2.y));
        acc_half4(acc1, h3, __uint_as_float(e3.y));
    }
    for (; i < e; i++) {
        uint2 e0 = __ldg(&g_edges[i]);
        uint2 h0 = __ldg((const uint2*)(g_support_h + (size_t)e0.x * D_OUT + coff) + lane);
        acc_half4(acc0, h0, __uint_as_float(e0.y));
    }

    float4 r4;
    r4.x = fmaxf(acc0[0] + acc1[0], 0.f);
    r4.y = fmaxf(acc0[1] + acc1[1], 0.f);
    r4.z = fmaxf(acc0[2] + acc1[2], 0.f);
    r4.w = fmaxf(acc0[3] + acc1[3], 0.f);
    __stcs((float4*)(out + (size_t)row * D_OUT + coff) + lane, r4);
}

// ---------------------------------------------------------------------------
// Launch: column-pipelined schedule.
//   S0: GEMM-A -> GEMM-B -> rowaccB ;  S2: CSR ;  S3: rowaccA (|| GEMM-B)
// ---------------------------------------------------------------------------
extern "C" void kernel_launch(void* const* d_in, const int* in_sizes, int n_in,
                              void* d_out, int out_size)
{
    static cudaStream_t s2 = nullptr, s3 = nullptr;
    static cudaEvent_t ev_fork = nullptr, ev_csr = nullptr,
                       ev_ga = nullptr, ev_ra = nullptr;
    static bool tried = false;
    if (!tried) {
        tried = true;
        bool ok = cudaStreamCreateWithFlags(&s2, cudaStreamNonBlocking) == cudaSuccess
               && cudaStreamCreateWithFlags(&s3, cudaStreamNonBlocking) == cudaSuccess
               && cudaEventCreateWithFlags(&ev_fork, cudaEventDisableTiming) == cudaSuccess
               && cudaEventCreateWithFlags(&ev_csr,  cudaEventDisableTiming) == cudaSuccess
               && cudaEventCreateWithFlags(&ev_ga,   cudaEventDisableTiming) == cudaSuccess
               && cudaEventCreateWithFlags(&ev_ra,   cudaEventDisableTiming) == cudaSuccess;
        if (!ok) s2 = nullptr;
    }
    const bool par = (s2 != nullptr);
    cudaStream_t cs  = par ? s2 : DEF_STREAM;   // CSR stream
    cudaStream_t rs  = par ? s3 : DEF_STREAM;   // rowaccA stream

    const float* features = (const float*)d_in[0];
    const float* weight   = (const float*)d_in[1];
    const void*  adj_row  = d_in[2];
    const void*  adj_col  = d_in[3];
    const float* adj_val  = (const float*)d_in[4];
    float* out = (float*)d_out;

    const int n_nodes = in_sizes[0] / D_IN;
    const int n_edges = in_sizes[4];

    detect_idx_kernel<<<1, 256>>>((const unsigned int*)adj_row);

    if (par) {
        cudaEventRecord(ev_fork, DEF_STREAM);
        cudaStreamWaitEvent(s2, ev_fork, 0);
    }

    // --- S2: CSR construction ---
    zero_counts_kernel<<<(n_nodes + 256) / 256, 256, 0, cs>>>(n_nodes);
    hist_kernel<<<(n_edges + 1023) / 1024, 256, 0, cs>>>(adj_row, n_edges);
    int nb = (n_nodes + SCAN_B - 1) / SCAN_B;
    scan_blocksum_kernel<<<nb, SCAN_B, 0, cs>>>(n_nodes);
    scan_offsets_kernel<<<1, 128, 0, cs>>>(nb, n_nodes);
    scan_write_kernel<<<nb, SCAN_B, 0, cs>>>(n_nodes);
    bucket_kernel<<<(n_edges + 255) / 256, 256, 0, cs>>>(adj_row, adj_col,
                                                         adj_val, n_edges);
    if (par) cudaEventRecord(ev_csr, s2);

    // --- S0: GEMM-A (support cols 0-127) ---
    dim3 ggrid(1, (n_nodes + GM - 1) / GM);
    gemm_tf32_kernel<<<ggrid, 256>>>(features, weight, n_nodes, 0);
    if (par) cudaEventRecord(ev_ga, DEF_STREAM);

    // --- S3: rowaccA (out cols 0-127), concurrent with GEMM-B ---
    if (par) {
        cudaStreamWaitEvent(s3, ev_ga, 0);
        cudaStreamWaitEvent(s3, ev_csr, 0);
    }
    // (in fallback mode this must come AFTER bucket+gemmA in program order — it does)

    // --- S0: GEMM-B (support cols 128-255) ---
    gemm_tf32_kernel<<<ggrid, 256>>>(features, weight, n_nodes, 128);

    rowacc_kernel<<<(n_nodes + 7) / 8, 256, 0, rs>>>(out, n_nodes, 0);
    if (par) cudaEventRecord(ev_ra, s3);

    // --- S0: rowaccB (out cols 128-255) after GEMM-B (+CSR) ---
    if (par) cudaStreamWaitEvent(DEF_STREAM, ev_csr, 0);
    rowacc_kernel<<<(n_nodes + 7) / 8, 256>>>(out, n_nodes, 128);

    if (par) cudaStreamWaitEvent(DEF_STREAM, ev_ra, 0);
}

// round 8
// speedup vs baseline: 8.3286x; 1.0296x over previous
#include <cuda_runtime.h>
#include <cuda_fp16.h>
#include <stdint.h>

#define N_NODES_MAX 100000
#define N_EDGES_MAX 3200000
#define D_IN 256
#define D_OUT 256

#if defined(CUDA_API_PER_THREAD_DEFAULT_STREAM) || defined(__CUDA_API_PER_THREAD_DEFAULT_STREAM__)
#define DEF_STREAM cudaStreamPerThread
#else
#define DEF_STREAM cudaStreamLegacy
#endif

// ---------------------------------------------------------------------------
// Static device scratch
// ---------------------------------------------------------------------------
__device__ __half g_support_h[(size_t)N_NODES_MAX * D_OUT];  // fp16 support
__device__ uint2  g_edges[N_EDGES_MAX];
__device__ int    g_count[N_NODES_MAX + 1];
__device__ int    g_start[N_NODES_MAX + 1];
__device__ int    g_cursor[N_NODES_MAX];
__device__ int    g_blocksum[128];
__device__ int    g_blockoff[128];
__device__ int    g_idx64;

// ---------------------------------------------------------------------------
// Index dtype detection
// ---------------------------------------------------------------------------
__global__ void detect_idx_kernel(const unsigned int* __restrict__ words) {
    __shared__ int any_nonzero;
    if (threadIdx.x == 0) any_nonzero = 0;
    __syncthreads();
    int local = 0;
    for (int i = threadIdx.x; i < 2048; i += blockDim.x)
        if (words[2 * i + 1] != 0u) local = 1;
    if (local) atomicOr(&any_nonzero, 1);
    __syncthreads();
    if (threadIdx.x == 0) g_idx64 = any_nonzero ? 0 : 1;
}

__device__ __forceinline__ int load_idx(const void* p, int i) {
    return g_idx64 ? (int)((const long long*)p)[i] : ((const int*)p)[i];
}

__device__ __forceinline__ float tf32r(float x) {
    uint32_t u;
    asm("cvt.rna.tf32.f32 %0, %1;" : "=r"(u) : "f"(x));
    return __uint_as_float(u);
}

// ---------------------------------------------------------------------------
// tf32 tensor-core GEMM over a 128-column slice of W.
// A is read with __ldcs (evict-first): zero reuse inside the kernel, and
// caching it would evict the fp16 support table that rowacc needs in L2.
// ---------------------------------------------------------------------------
#define GM 128
#define GN 128
#define GK 32
#define AS_STRIDE 36
#define BS_STRIDE 136

__global__ __launch_bounds__(256) void gemm_tf32_kernel(
    const float* __restrict__ A, const float* __restrict__ W, int M, int bn0)
{
    __shared__ __align__(16) float As[GM * AS_STRIDE];
    __shared__ __align__(16) float Bs[GK * BS_STRIDE];

    const int tid  = threadIdx.x;
    const int wid  = tid >> 5;
    const int lane = tid & 31;
    const int g    = lane >> 2;
    const int tg   = lane & 3;
    const int warp_m = (wid & 3) * 32;
    const int warp_n = (wid >> 2) * 64;
    const int bm = blockIdx.y * GM;
    const int bn = bn0;

    float c[2][8][4];
    #pragma unroll
    for (int mi = 0; mi < 2; mi++)
        #pragma unroll
        for (int ni = 0; ni < 8; ni++)
            #pragma unroll
            for (int r = 0; r < 4; r++) c[mi][ni][r] = 0.0f;

    for (int k0 = 0; k0 < D_IN; k0 += GK) {
        #pragma unroll
        for (int l = 0; l < 4; l++) {
            int idx = tid + l * 256;
            int row = idx >> 3, c4 = idx & 7;
            float4 v = make_float4(0.f, 0.f, 0.f, 0.f);
            int m = bm + row;
            if (m < M)
                v = __ldcs((const float4*)(A + (size_t)m * D_IN + k0 + c4 * 4));
            float4 t = make_float4(tf32r(v.x), tf32r(v.y), tf32r(v.z), tf32r(v.w));
            *(float4*)(As + row * AS_STRIDE + c4 * 4) = t;
        }
        #pragma unroll
        for (int l = 0; l < 4; l++) {
            int idx = tid + l * 256;
            int row = idx >> 5, c4 = idx & 31;
            float4 v = *(const float4*)(W + (size_t)(k0 + row) * D_OUT + bn + c4 * 4);
            float4 t = make_float4(tf32r(v.x), tf32r(v.y), tf32r(v.z), tf32r(v.w));
            *(float4*)(Bs + row * BS_STRIDE + c4 * 4) = t;
        }
        __syncthreads();

        #pragma unroll
        for (int ks = 0; ks < 4; ks++) {
            const int kb = ks * 8;
            uint32_t a[2][4], b[8][2];
            #pragma unroll
            for (int mi = 0; mi < 2; mi++) {
                int r = warp_m + mi * 16;
                a[mi][0] = __float_as_uint(As[(r + g)     * AS_STRIDE + kb + tg]);
                a[mi][1] = __float_as_uint(As[(r + g + 8) * AS_STRIDE + kb + tg]);
                a[mi][2] = __float_as_uint(As[(r + g)     * AS_STRIDE + kb + tg + 4]);
                a[mi][3] = __float_as_uint(As[(r + g + 8) * AS_STRIDE + kb + tg + 4]);
            }
            #pragma unroll
            for (int ni = 0; ni < 8; ni++) {
                int col = warp_n + ni * 8 + g;
                b[ni][0] = __float_as_uint(Bs[(kb + tg)     * BS_STRIDE + col]);
                b[ni][1] = __float_as_uint(Bs[(kb + tg + 4) * BS_STRIDE + col]);
            }
            #pragma unroll
            for (int mi = 0; mi < 2; mi++)
                #pragma unroll
                for (int ni = 0; ni < 8; ni++) {
                    asm volatile(
                        "mma.sync.aligned.m16n8k8.row.col.f32.tf32.tf32.f32 "
                        "{%0,%1,%2,%3}, {%4,%5,%6,%7}, {%8,%9}, {%0,%1,%2,%3};\n"
                        : "+f"(c[mi][ni][0]), "+f"(c[mi][ni][1]),
                          "+f"(c[mi][ni][2]), "+f"(c[mi][ni][3])
                        : "r"(a[mi][0]), "r"(a[mi][1]), "r"(a[mi][2]), "r"(a[mi][3]),
                          "r"(b[ni][0]), "r"(b[ni][1]));
                }
        }
        __syncthreads();
    }

    #pragma unroll
    for (int mi = 0; mi < 2; mi++) {
        int r0 = bm + warp_m + mi * 16 + g;
        #pragma unroll
        for (int ni = 0; ni < 8; ni++) {
            int col = bn + warp_n + ni * 8 + tg * 2;
            if (r0 < M)
                *(__half2*)(g_support_h + (size_t)r0 * D_OUT + col) =
                    __floats2half2_rn(c[mi][ni][0], c[mi][ni][1]);
            if (r0 + 8 < M)
                *(__half2*)(g_support_h + (size_t)(r0 + 8) * D_OUT + col) =
                    __floats2half2_rn(c[mi][ni][2], c[mi][ni][3]);
        }
    }
}

// ---------------------------------------------------------------------------
// CSR construction
// ---------------------------------------------------------------------------
__global__ void zero_counts_kernel(int n) {
    int i = blockIdx.x * blockDim.x + threadIdx.x;
    if (i <= n) g_count[i] = 0;
}

__global__ void hist_kernel(const void* __restrict__ adj_row, int n_edges) {
    int base = (blockIdx.x * blockDim.x + threadIdx.x) * 4;
    #pragma unroll
    for (int k = 0; k < 4; k++) {
        int e = base + k;
        if (e < n_edges) atomicAdd(&g_count[load_idx(adj_row, e)], 1);
    }
}

#define SCAN_B 1024

__global__ __launch_bounds__(SCAN_B) void scan_blocksum_kernel(int n) {
    int i = blockIdx.x * SCAN_B + threadIdx.x;
    int lane = threadIdx.x & 31, wid = threadIdx.x >> 5;
    int v = (i < n) ? g_count[i] : 0;
    #pragma unroll
    for (int o = 16; o > 0; o >>= 1) v += __shfl_down_sync(~0u, v, o);
    __shared__ int ws[32];
    if (lane == 0) ws[wid] = v;
    __syncthreads();
    if (wid == 0) {
        int s = ws[lane];
        #pragma unroll
        for (int o = 16; o > 0; o >>= 1) s += __shfl_down_sync(~0u, s, o);
        if (lane == 0) g_blocksum[blockIdx.x] = s;
    }
}

__global__ __launch_bounds__(128) void scan_offsets_kernel(int nb, int n) {
    int tid = threadIdx.x, lane = tid & 31, wid = tid >> 5;
    int v = (tid < nb) ? g_blocksum[tid] : 0;
    int incl = v;
    #pragma unroll
    for (int o = 1; o < 32; o <<= 1) {
        int t = __shfl_up_sync(~0u, incl, o);
        if (lane >= o) incl += t;
    }
    __shared__ int ws[4];
    if (lane == 31) ws[wid] = incl;
    __syncthreads();
    int woff = 0;
    for (int w = 0; w < wid; w++) woff += ws[w];
    incl += woff;
    g_blockoff[tid] = incl - v;
    if (tid == nb - 1) g_start[n] = incl;
}

__global__ __launch_bounds__(SCAN_B) void scan_write_kernel(int n) {
    int b = blockIdx.x;
    int i = b * SCAN_B + threadIdx.x;
    int lane = threadIdx.x & 31, wid = threadIdx.x >> 5;
    int v = (i < n) ? g_count[i] : 0;
    int incl = v;
    #pragma unroll
    for (int o = 1; o < 32; o <<= 1) {
        int t = __shfl_up_sync(~0u, incl, o);
        if (lane >= o) incl += t;
    }
    __shared__ int ws[32];
    __shared__ int woff[32];
    if (lane == 31) ws[wid] = incl;
    __syncthreads();
    if (wid == 0) {
        int s = ws[lane];
        int si = s;
        #pragma unroll
        for (int o = 1; o < 32; o <<= 1) {
            int t = __shfl_up_sync(~0u, si, o);
            if (lane >= o) si += t;
        }
        woff[lane] = si - s;
    }
    __syncthreads();
    int excl = incl - v + woff[wid] + g_blockoff[b];
    if (i < n) { g_start[i] = excl; g_cursor[i] = excl; }
}

// 2 edges per thread for load MLP on the critical pre-rowacc path.
__global__ void bucket_kernel(const void* __restrict__ adj_row,
                              const void* __restrict__ adj_col,
                              const float* __restrict__ adj_val, int n_edges)
{
    int base = (blockIdx.x * blockDim.x + threadIdx.x) * 2;
    #pragma unroll
    for (int k = 0; k < 2; k++) {
        int e = base + k;
        if (e < n_edges) {
            int r = load_idx(adj_row, e);
            int c = load_idx(adj_col, e);
            int pos = atomicAdd(&g_cursor[r], 1);
            g_edges[pos] = make_uint2((unsigned)c, __float_as_uint(adj_val[e]));
        }
    }
}

// ---------------------------------------------------------------------------
// Row accumulate over a 128-column slice (coff = 0 or 128).
// ---------------------------------------------------------------------------
__device__ __forceinline__ void acc_half4(float* acc, uint2 h, float v) {
    float2 f;
    f = __half22float2(*(__half2*)&h.x); acc[0] += v * f.x; acc[1] += v * f.y;
    f = __half22float2(*(__half2*)&h.y); acc[2] += v * f.x; acc[3] += v * f.y;
}

__global__ __launch_bounds__(256) void rowacc_kernel(float* __restrict__ out,
                                                     int n_nodes, int coff)
{
    const int sub  = threadIdx.x >> 5;
    const int lane = threadIdx.x & 31;
    const int row  = blockIdx.x * 8 + sub;
    if (row >= n_nodes) return;

    const int s = g_start[row];
    const int e = g_start[row + 1];

    float acc0[4], acc1[4];
    #pragma unroll
    for (int k = 0; k < 4; k++) { acc0[k] = 0.f; acc1[k] = 0.f; }

    int i = s;
    for (; i + 3 < e; i += 4) {
        uint2 e0 = __ldg(&g_edges[i]);
        uint2 e1 = __ldg(&g_edges[i + 1]);
        uint2 e2 = __ldg(&g_edges[i + 2]);
        uint2 e3 = __ldg(&g_edges[i + 3]);
        uint2 h0 = __ldg((const uint2*)(g_support_h + (size_t)e0.x * D_OUT + coff) + lane);
        uint2 h1 = __ldg((const uint2*)(g_support_h + (size_t)e1.x * D_OUT + coff) + lane);
        uint2 h2 = __ldg((const uint2*)(g_support_h + (size_t)e2.x * D_OUT + coff) + lane);
        uint2 h3 = __ldg((const uint2*)(g_support_h + (size_t)e3.x * D_OUT + coff) + lane);

        acc_half4(acc0, h0, __uint_as_float(e0.y));
        acc_half4(acc1, h1, __uint_as_float(e1.y));
        acc_half4(acc0, h2, __uint_as_float(e2.y));
        acc_half4(acc1, h3, __uint_as_float(e3.y));
    }
    for (; i < e; i++) {
        uint2 e0 = __ldg(&g_edges[i]);
        uint2 h0 = __ldg((const uint2*)(g_support_h + (size_t)e0.x * D_OUT + coff) + lane);
        acc_half4(acc0, h0, __uint_as_float(e0.y));
    }

    float4 r4;
    r4.x = fmaxf(acc0[0] + acc1[0], 0.f);
    r4.y = fmaxf(acc0[1] + acc1[1], 0.f);
    r4.z = fmaxf(acc0[2] + acc1[2], 0.f);
    r4.w = fmaxf(acc0[3] + acc1[3], 0.f);
    __stcs((float4*)(out + (size_t)row * D_OUT + coff) + lane, r4);
}

// ---------------------------------------------------------------------------
// Launch: column pipeline with L2-protected overlap + priority arbitration.
//   S0: GEMM-A -> GEMM-B -> rowaccB ;  S2: CSR ;  S3(high prio): rowaccA
// ---------------------------------------------------------------------------
extern "C" void kernel_launch(void* const* d_in, const int* in_sizes, int n_in,
                              void* d_out, int out_size)
{
    static cudaStream_t s2 = nullptr, s3 = nullptr;
    static cudaEvent_t ev_fork = nullptr, ev_csr = nullptr,
                       ev_ga = nullptr, ev_ra = nullptr;
    static bool tried = false;
    if (!tried) {
        tried = true;
        int lo = 0, hi = 0;
        cudaDeviceGetStreamPriorityRange(&lo, &hi);   // hi = greatest priority
        bool ok = cudaStreamCreateWithPriority(&s2, cudaStreamNonBlocking, 0) == cudaSuccess
               && cudaStreamCreateWithPriority(&s3, cudaStreamNonBlocking, hi) == cudaSuccess
               && cudaEventCreateWithFlags(&ev_fork, cudaEventDisableTiming) == cudaSuccess
               && cudaEventCreateWithFlags(&ev_csr,  cudaEventDisableTiming) == cudaSuccess
               && cudaEventCreateWithFlags(&ev_ga,   cudaEventDisableTiming) == cudaSuccess
               && cudaEventCreateWithFlags(&ev_ra,   cudaEventDisableTiming) == cudaSuccess;
        if (!ok) s2 = nullptr;
    }
    const bool par = (s2 != nullptr);
    cudaStream_t cs = par ? s2 : DEF_STREAM;
    cudaStream_t rs = par ? s3 : DEF_STREAM;

    const float* features = (const float*)d_in[0];
    const float* weight   = (const float*)d_in[1];
    const void*  adj_row  = d_in[2];
    const void*  adj_col  = d_in[3];
    const float* adj_val  = (const float*)d_in[4];
    float* out = (float*)d_out;

    const int n_nodes = in_sizes[0] / D_IN;
    const int n_edges = in_sizes[4];

    detect_idx_kernel<<<1, 256>>>((const unsigned int*)adj_row);

    if (par) {
        cudaEventRecord(ev_fork, DEF_STREAM);
        cudaStreamWaitEvent(s2, ev_fork, 0);
    }

    // --- S2: CSR construction ---
    zero_counts_kernel<<<(n_nodes + 256) / 256, 256, 0, cs>>>(n_nodes);
    hist_kernel<<<(n_edges + 1023) / 1024, 256, 0, cs>>>(adj_row, n_edges);
    int nb = (n_nodes + SCAN_B - 1) / SCAN_B;
    scan_blocksum_kernel<<<nb, SCAN_B, 0, cs>>>(n_nodes);
    scan_offsets_kernel<<<1, 128, 0, cs>>>(nb, n_nodes);
    scan_write_kernel<<<nb, SCAN_B, 0, cs>>>(n_nodes);
    bucket_kernel<<<(n_edges + 511) / 512, 256, 0, cs>>>(adj_row, adj_col,
                                                         adj_val, n_edges);
    if (par) cudaEventRecord(ev_csr, s2);

    // --- S0: GEMM-A (support cols 0-127) ---
    dim3 ggrid(1, (n_nodes + GM - 1) / GM);
    gemm_tf32_kernel<<<ggrid, 256>>>(features, weight, n_nodes, 0);
    if (par) cudaEventRecord(ev_ga, DEF_STREAM);

    // --- S3 (high priority): rowaccA — enqueued BEFORE GEMM-B so its blocks
    // win dispatch arbitration once ev_ga + ev_csr fire.
    if (par) {
        cudaStreamWaitEvent(s3, ev_ga, 0);
        cudaStreamWaitEvent(s3, ev_csr, 0);
    } else {
        // fallback: serialize GEMM-B before rowaccA on the single stream
        gemm_tf32_kernel<<<ggrid, 256>>>(features, weight, n_nodes, 128);
    }
    rowacc_kernel<<<(n_nodes + 7) / 8, 256, 0, rs>>>(out, n_nodes, 0);
    if (par) cudaEventRecord(ev_ra, s3);

    // --- S0: GEMM-B (support cols 128-255), concurrent with rowaccA ---
    if (par) gemm_tf32_kernel<<<ggrid, 256>>>(features, weight, n_nodes, 128);

    // --- S0: rowaccB after GEMM-B (+CSR) ---
    if (par) cudaStreamWaitEvent(DEF_STREAM, ev_csr, 0);
    rowacc_kernel<<<(n_nodes + 7) / 8, 256>>>(out, n_nodes, 128);

    if (par) cudaStreamWaitEvent(DEF_STREAM, ev_ra, 0);
}

// round 9
// speedup vs baseline: 9.1148x; 1.0944x over previous
#include <cuda_runtime.h>
#include <cuda_fp16.h>
#include <stdint.h>

#define N_NODES_MAX 100000
#define N_EDGES_MAX 3200000
#define D_IN 256
#define D_OUT 256

#if defined(CUDA_API_PER_THREAD_DEFAULT_STREAM) || defined(__CUDA_API_PER_THREAD_DEFAULT_STREAM__)
#define DEF_STREAM cudaStreamPerThread
#else
#define DEF_STREAM cudaStreamLegacy
#endif

// ---------------------------------------------------------------------------
// Static device scratch
// ---------------------------------------------------------------------------
__device__ __half g_support_h[(size_t)N_NODES_MAX * D_OUT];  // fp16 support
__device__ uint2  g_edges[N_EDGES_MAX];
__device__ int    g_count[N_NODES_MAX + 1];
__device__ int    g_start[N_NODES_MAX + 1];
__device__ int    g_cursor[N_NODES_MAX];
__device__ int    g_blocksum[128];
__device__ int    g_blockoff[128];
__device__ int    g_idx64;

// ---------------------------------------------------------------------------
// Fused: zero g_count (all blocks) + index dtype detection (block 0)
// ---------------------------------------------------------------------------
__global__ void detect_zero_kernel(const unsigned int* __restrict__ words, int n) {
    int i = blockIdx.x * blockDim.x + threadIdx.x;
    if (i <= n) g_count[i] = 0;
    if (blockIdx.x == 0) {
        __shared__ int any_nonzero;
        if (threadIdx.x == 0) any_nonzero = 0;
        __syncthreads();
        int local = 0;
        for (int k = threadIdx.x; k < 2048; k += blockDim.x)
            if (words[2 * k + 1] != 0u) local = 1;
        if (local) atomicOr(&any_nonzero, 1);
        __syncthreads();
        if (threadIdx.x == 0) g_idx64 = any_nonzero ? 0 : 1;
    }
}

__device__ __forceinline__ int load_idx(const void* p, int i) {
    return g_idx64 ? (int)((const long long*)p)[i] : ((const int*)p)[i];
}

// ---------------------------------------------------------------------------
// tf32 tensor-core GEMM over a 128-column slice of W, 2-stage cp.async
// pipeline. A streamed with L2 evict_first (zero reuse; protects the fp16
// support table in L2). tf32 rna conversion happens at fragment load (fma/alu
// pipe, overlapped with tensor pipe).
// ---------------------------------------------------------------------------
#define GM 128
#define GN 128
#define GK 32
#define AS_STRIDE 36
#define BS_STRIDE 136
#define ASZ (GM * AS_STRIDE)   // 4608 floats
#define BSZ (GK * BS_STRIDE)   // 4352 floats
#define GEMM_SMEM_BYTES ((2 * ASZ + 2 * BSZ) * 4)   // 71680 B

__device__ __forceinline__ uint32_t smem_u32(const void* p) {
    return (uint32_t)__cvta_generic_to_shared(p);
}

__device__ __forceinline__ void cp16_evict_first(uint32_t dst, const void* src,
                                                 int src_bytes, uint64_t pol) {
    asm volatile(
        "cp.async.cg.shared.global.L2::cache_hint [%0], [%1], 16, %2, %3;"
        :: "r"(dst), "l"(src), "r"(src_bytes), "l"(pol));
}

__device__ __forceinline__ void cp16(uint32_t dst, const void* src) {
    asm volatile("cp.async.cg.shared.global [%0], [%1], 16;"
                 :: "r"(dst), "l"(src));
}

__device__ __forceinline__ uint32_t ld_tf32(const float* p) {
    uint32_t u;
    asm("cvt.rna.tf32.f32 %0, %1;" : "=r"(u) : "f"(*p));
    return u;
}

__global__ __launch_bounds__(256, 2) void gemm_tf32_kernel(
    const float* __restrict__ A, const float* __restrict__ W, int M, int bn0)
{
    extern __shared__ float smem[];
    float* As[2] = { smem,            smem + ASZ };
    float* Bs[2] = { smem + 2 * ASZ,  smem + 2 * ASZ + BSZ };

    uint64_t pol;
    asm("createpolicy.fractional.L2::evict_first.b64 %0, 1.0;" : "=l"(pol));

    const int tid  = threadIdx.x;
    const int wid  = tid >> 5;
    const int lane = tid & 31;
    const int g    = lane >> 2;
    const int tg   = lane & 3;
    const int warp_m = (wid & 3) * 32;
    const int warp_n = (wid >> 2) * 64;
    const int bm = blockIdx.y * GM;
    const int bn = bn0;

    float c[2][8][4];
    #pragma unroll
    for (int mi = 0; mi < 2; mi++)
        #pragma unroll
        for (int ni = 0; ni < 8; ni++)
            #pragma unroll
            for (int r = 0; r < 4; r++) c[mi][ni][r] = 0.0f;

    // --- tile issue: A[bm:bm+128, k0:k0+32], W[k0:k0+32, bn:bn+128] ---
    auto issue_tile = [&](int k0, int buf) {
        #pragma unroll
        for (int l = 0; l < 4; l++) {
            int idx = tid + l * 256;
            int row = idx >> 3, c4 = idx & 7;
            int m = bm + row;
            int mc = (m < M) ? m : (M - 1);
            cp16_evict_first(
                smem_u32(As[buf] + row * AS_STRIDE + c4 * 4),
                A + (size_t)mc * D_IN + k0 + c4 * 4,
                (m < M) ? 16 : 0, pol);
        }
        #pragma unroll
        for (int l = 0; l < 4; l++) {
            int idx = tid + l * 256;
            int row = idx >> 5, c4 = idx & 31;
            cp16(smem_u32(Bs[buf] + row * BS_STRIDE + c4 * 4),
                 W + (size_t)(k0 + row) * D_OUT + bn + c4 * 4);
        }
        asm volatile("cp.async.commit_group;");
    };

    issue_tile(0, 0);

    #pragma unroll
    for (int t = 0; t < D_IN / GK; t++) {
        if (t + 1 < D_IN / GK) {
            issue_tile((t + 1) * GK, (t + 1) & 1);
            asm volatile("cp.async.wait_group 1;");
        } else {
            asm volatile("cp.async.wait_group 0;");
        }
        __syncthreads();

        const float* as = As[t & 1];
        const float* bs = Bs[t & 1];
        #pragma unroll
        for (int ks = 0; ks < 4; ks++) {
            const int kb = ks * 8;
            uint32_t a[2][4], b[8][2];
            #pragma unroll
            for (int mi = 0; mi < 2; mi++) {
                int r = warp_m + mi * 16;
                a[mi][0] = ld_tf32(&as[(r + g)     * AS_STRIDE + kb + tg]);
                a[mi][1] = ld_tf32(&as[(r + g + 8) * AS_STRIDE + kb + tg]);
                a[mi][2] = ld_tf32(&as[(r + g)     * AS_STRIDE + kb + tg + 4]);
                a[mi][3] = ld_tf32(&as[(r + g + 8) * AS_STRIDE + kb + tg + 4]);
            }
            #pragma unroll
            for (int ni = 0; ni < 8; ni++) {
                int col = warp_n + ni * 8 + g;
                b[ni][0] = ld_tf32(&bs[(kb + tg)     * BS_STRIDE + col]);
                b[ni][1] = ld_tf32(&bs[(kb + tg + 4) * BS_STRIDE + col]);
            }
            #pragma unroll
            for (int mi = 0; mi < 2; mi++)
                #pragma unroll
                for (int ni = 0; ni < 8; ni++) {
                    asm volatile(
                        "mma.sync.aligned.m16n8k8.row.col.f32.tf32.tf32.f32 "
                        "{%0,%1,%2,%3}, {%4,%5,%6,%7}, {%8,%9}, {%0,%1,%2,%3};\n"
                        : "+f"(c[mi][ni][0]), "+f"(c[mi][ni][1]),
                          "+f"(c[mi][ni][2]), "+f"(c[mi][ni][3])
                        : "r"(a[mi][0]), "r"(a[mi][1]), "r"(a[mi][2]), "r"(a[mi][3]),
                          "r"(b[ni][0]), "r"(b[ni][1]));
                }
        }
        __syncthreads();
    }

    #pragma unroll
    for (int mi = 0; mi < 2; mi++) {
        int r0 = bm + warp_m + mi * 16 + g;
        #pragma unroll
        for (int ni = 0; ni < 8; ni++) {
            int col = bn + warp_n + ni * 8 + tg * 2;
            if (r0 < M)
                *(__half2*)(g_support_h + (size_t)r0 * D_OUT + col) =
                    __floats2half2_rn(c[mi][ni][0], c[mi][ni][1]);
            if (r0 + 8 < M)
                *(__half2*)(g_support_h + (size_t)(r0 + 8) * D_OUT + col) =
                    __floats2half2_rn(c[mi][ni][2], c[mi][ni][3]);
        }
    }
}

// ---------------------------------------------------------------------------
// CSR construction
// ---------------------------------------------------------------------------
__global__ void hist_kernel(const void* __restrict__ adj_row, int n_edges) {
    int base = (blockIdx.x * blockDim.x + threadIdx.x) * 4;
    #pragma unroll
    for (int k = 0; k < 4; k++) {
        int e = base + k;
        if (e < n_edges) atomicAdd(&g_count[load_idx(adj_row, e)], 1);
    }
}

#define SCAN_B 1024

__global__ __launch_bounds__(SCAN_B) void scan_blocksum_kernel(int n) {
    int i = blockIdx.x * SCAN_B + threadIdx.x;
    int lane = threadIdx.x & 31, wid = threadIdx.x >> 5;
    int v = (i < n) ? g_count[i] : 0;
    #pragma unroll
    for (int o = 16; o > 0; o >>= 1) v += __shfl_down_sync(~0u, v, o);
    __shared__ int ws[32];
    if (lane == 0) ws[wid] = v;
    __syncthreads();
    if (wid == 0) {
        int s = ws[lane];
        #pragma unroll
        for (int o = 16; o > 0; o >>= 1) s += __shfl_down_sync(~0u, s, o);
        if (lane == 0) g_blocksum[blockIdx.x] = s;
    }
}

__global__ __launch_bounds__(128) void scan_offsets_kernel(int nb, int n) {
    int tid = threadIdx.x, lane = tid & 31, wid = tid >> 5;
    int v = (tid < nb) ? g_blocksum[tid] : 0;
    int incl = v;
    #pragma unroll
    for (int o = 1; o < 32; o <<= 1) {
        int t = __shfl_up_sync(~0u, incl, o);
        if (lane >= o) incl += t;
    }
    __shared__ int ws[4];
    if (lane == 31) ws[wid] = incl;
    __syncthreads();
    int woff = 0;
    for (int w = 0; w < wid; w++) woff += ws[w];
    incl += woff;
    g_blockoff[tid] = incl - v;
    if (tid == nb - 1) g_start[n] = incl;
}

__global__ __launch_bounds__(SCAN_B) void scan_write_kernel(int n) {
    int b = blockIdx.x;
    int i = b * SCAN_B + threadIdx.x;
    int lane = threadIdx.x & 31, wid = threadIdx.x >> 5;
    int v = (i < n) ? g_count[i] : 0;
    int incl = v;
    #pragma unroll
    for (int o = 1; o < 32; o <<= 1) {
        int t = __shfl_up_sync(~0u, incl, o);
        if (lane >= o) incl += t;
    }
    __shared__ int ws[32];
    __shared__ int woff[32];
    if (lane == 31) ws[wid] = incl;
    __syncthreads();
    if (wid == 0) {
        int s = ws[lane];
        int si = s;
        #pragma unroll
        for (int o = 1; o < 32; o <<= 1) {
            int t = __shfl_up_sync(~0u, si, o);
            if (lane >= o) si += t;
        }
        woff[lane] = si - s;
    }
    __syncthreads();
    int excl = incl - v + woff[wid] + g_blockoff[b];
    if (i < n) { g_start[i] = excl; g_cursor[i] = excl; }
}

__global__ void bucket_kernel(const void* __restrict__ adj_row,
                              const void* __restrict__ adj_col,
                              const float* __restrict__ adj_val, int n_edges)
{
    int base = (blockIdx.x * blockDim.x + threadIdx.x) * 2;
    #pragma unroll
    for (int k = 0; k < 2; k++) {
        int e = base + k;
        if (e < n_edges) {
            int r = load_idx(adj_row, e);
            int c = load_idx(adj_col, e);
            int pos = atomicAdd(&g_cursor[r], 1);
            g_edges[pos] = make_uint2((unsigned)c, __float_as_uint(adj_val[e]));
        }
    }
}

// ---------------------------------------------------------------------------
// Row accumulate over a 128-column slice (coff = 0 or 128).
// ---------------------------------------------------------------------------
__device__ __forceinline__ void acc_half4(float* acc, uint2 h, float v) {
    float2 f;
    f = __half22float2(*(__half2*)&h.x); acc[0] += v * f.x; acc[1] += v * f.y;
    f = __half22float2(*(__half2*)&h.y); acc[2] += v * f.x; acc[3] += v * f.y;
}

__global__ __launch_bounds__(256) void rowacc_kernel(float* __restrict__ out,
                                                     int n_nodes, int coff)
{
    const int sub  = threadIdx.x >> 5;
    const int lane = threadIdx.x & 31;
    const int row  = blockIdx.x * 8 + sub;
    if (row >= n_nodes) return;

    const int s = g_start[row];
    const int e = g_start[row + 1];

    float acc0[4], acc1[4];
    #pragma unroll
    for (int k = 0; k < 4; k++) { acc0[k] = 0.f; acc1[k] = 0.f; }

    int i = s;
    for (; i + 3 < e; i += 4) {
        uint2 e0 = __ldg(&g_edges[i]);
        uint2 e1 = __ldg(&g_edges[i + 1]);
        uint2 e2 = __ldg(&g_edges[i + 2]);
        uint2 e3 = __ldg(&g_edges[i + 3]);
        uint2 h0 = __ldg((const uint2*)(g_support_h + (size_t)e0.x * D_OUT + coff) + lane);
        uint2 h1 = __ldg((const uint2*)(g_support_h + (size_t)e1.x * D_OUT + coff) + lane);
        uint2 h2 = __ldg((const uint2*)(g_support_h + (size_t)e2.x * D_OUT + coff) + lane);
        uint2 h3 = __ldg((const uint2*)(g_support_h + (size_t)e3.x * D_OUT + coff) + lane);

        acc_half4(acc0, h0, __uint_as_float(e0.y));
        acc_half4(acc1, h1, __uint_as_float(e1.y));
        acc_half4(acc0, h2, __uint_as_float(e2.y));
        acc_half4(acc1, h3, __uint_as_float(e3.y));
    }
    for (; i < e; i++) {
        uint2 e0 = __ldg(&g_edges[i]);
        uint2 h0 = __ldg((const uint2*)(g_support_h + (size_t)e0.x * D_OUT + coff) + lane);
        acc_half4(acc0, h0, __uint_as_float(e0.y));
    }

    float4 r4;
    r4.x = fmaxf(acc0[0] + acc1[0], 0.f);
    r4.y = fmaxf(acc0[1] + acc1[1], 0.f);
    r4.z = fmaxf(acc0[2] + acc1[2], 0.f);
    r4.w = fmaxf(acc0[3] + acc1[3], 0.f);
    __stcs((float4*)(out + (size_t)row * D_OUT + coff) + lane, r4);
}

// ---------------------------------------------------------------------------
// Launch: column pipeline with L2-protected overlap + priority arbitration.
// ---------------------------------------------------------------------------
extern "C" void kernel_launch(void* const* d_in, const int* in_sizes, int n_in,
                              void* d_out, int out_size)
{
    static cudaStream_t s2 = nullptr, s3 = nullptr;
    static cudaEvent_t ev_fork = nullptr, ev_csr = nullptr,
                       ev_ga = nullptr, ev_ra = nullptr;
    static bool tried = false;
    if (!tried) {
        tried = true;
        int lo = 0, hi = 0;
        cudaDeviceGetStreamPriorityRange(&lo, &hi);
        bool ok = cudaStreamCreateWithPriority(&s2, cudaStreamNonBlocking, 0) == cudaSuccess
               && cudaStreamCreateWithPriority(&s3, cudaStreamNonBlocking, hi) == cudaSuccess
               && cudaEventCreateWithFlags(&ev_fork, cudaEventDisableTiming) == cudaSuccess
               && cudaEventCreateWithFlags(&ev_csr,  cudaEventDisableTiming) == cudaSuccess
               && cudaEventCreateWithFlags(&ev_ga,   cudaEventDisableTiming) == cudaSuccess
               && cudaEventCreateWithFlags(&ev_ra,   cudaEventDisableTiming) == cudaSuccess;
        if (!ok) s2 = nullptr;
        cudaFuncSetAttribute(gemm_tf32_kernel,
                             cudaFuncAttributeMaxDynamicSharedMemorySize,
                             GEMM_SMEM_BYTES);
    }
    const bool par = (s2 != nullptr);
    cudaStream_t cs = par ? s2 : DEF_STREAM;
    cudaStream_t rs = par ? s3 : DEF_STREAM;

    const float* features = (const float*)d_in[0];
    const float* weight   = (const float*)d_in[1];
    const void*  adj_row  = d_in[2];
    const void*  adj_col  = d_in[3];
    const float* adj_val  = (const float*)d_in[4];
    float* out = (float*)d_out;

    const int n_nodes = in_sizes[0] / D_IN;
    const int n_edges = in_sizes[4];

    // Fused zero(g_count) + dtype detection
    detect_zero_kernel<<<(n_nodes + 256) / 256, 256>>>(
        (const unsigned int*)adj_row, n_nodes);

    if (par) {
        cudaEventRecord(ev_fork, DEF_STREAM);
        cudaStreamWaitEvent(s2, ev_fork, 0);
    }

    // --- S2: CSR construction ---
    hist_kernel<<<(n_edges + 1023) / 1024, 256, 0, cs>>>(adj_row, n_edges);
    int nb = (n_nodes + SCAN_B - 1) / SCAN_B;
    scan_blocksum_kernel<<<nb, SCAN_B, 0, cs>>>(n_nodes);
    scan_offsets_kernel<<<1, 128, 0, cs>>>(nb, n_nodes);
    scan_write_kernel<<<nb, SCAN_B, 0, cs>>>(n_nodes);
    bucket_kernel<<<(n_edges + 511) / 512, 256, 0, cs>>>(adj_row, adj_col,
                                                         adj_val, n_edges);
    if (par) cudaEventRecord(ev_csr, s2);

    // --- S0: GEMM-A (support cols 0-127) ---
    dim3 ggrid(1, (n_nodes + GM - 1) / GM);
    gemm_tf32_kernel<<<ggrid, 256, GEMM_SMEM_BYTES>>>(features, weight,
                                                      n_nodes, 0);
    if (par) cudaEventRecord(ev_ga, DEF_STREAM);

    // --- S3 (high priority): rowaccA after GEMM-A + CSR ---
    if (par) {
        cudaStreamWaitEvent(s3, ev_ga, 0);
        cudaStreamWaitEvent(s3, ev_csr, 0);
    } else {
        gemm_tf32_kernel<<<ggrid, 256, GEMM_SMEM_BYTES>>>(features, weight,
                                                          n_nodes, 128);
    }
    rowacc_kernel<<<(n_nodes + 7) / 8, 256, 0, rs>>>(out, n_nodes, 0);
    if (par) cudaEventRecord(ev_ra, s3);

    // --- S0: GEMM-B (support cols 128-255), concurrent with rowaccA ---
    if (par) gemm_tf32_kernel<<<ggrid, 256, GEMM_SMEM_BYTES>>>(features, weight,
                                                               n_nodes, 128);

    // --- S0: rowaccB after GEMM-B (+CSR) ---
    if (par) cudaStreamWaitEvent(DEF_STREAM, ev_csr, 0);
    rowacc_kernel<<<(n_nodes + 7) / 8, 256>>>(out, n_nodes, 128);

    if (par) cudaStreamWaitEvent(DEF_STREAM, ev_ra, 0);
}